// round 9
// baseline (speedup 1.0000x reference)
#include <cuda_runtime.h>
#include <cuda_bf16.h>
#include <math.h>
#include <stdint.h>

// ---------------- constants ----------------
constexpr int kB   = 128;
constexpr int kT   = 196;
constexpr int kC   = 768;
constexpr int kHID = 3072;
constexpr int kH   = 14;
constexpr int kW   = 14;
constexpr int kN   = kB * kT;        // 25088 rows
constexpr int kNC  = kN * kC;
constexpr int kNH  = kN * kHID;
constexpr int kBC  = kB * kC;
constexpr float kEPS = 1e-5f;

// ---------------- scratch (device globals) ----------------
__device__ float g_x0[kNC];
__device__ float g_xi[kNC];
__device__ float g_k [kNC];
__device__ float g_v [kNC];
__device__ float g_sr[kNC];
__device__ float g_tA[kNC];
__device__ float g_tB[kNC];
__device__ float g_rw[kNC];
__device__ float g_hid[kNH];
// bf16 activation planes (hi/lo)
__device__ __nv_bfloat16 g_ak_h[kNC], g_ak_l[kNC];
__device__ __nv_bfloat16 g_av_h[kNC], g_av_l[kNC];
__device__ __nv_bfloat16 g_ar_h[kNC], g_ar_l[kNC];
__device__ __nv_bfloat16 g_hh  [kNH], g_hl  [kNH];
// bf16 transposed weight planes [Mout, K]
__device__ __nv_bfloat16 g_wk_h[kC*kC],  g_wk_l[kC*kC];
__device__ __nv_bfloat16 g_wv_h[kC*kC],  g_wv_l[kC*kC];
__device__ __nv_bfloat16 g_wr_h[kC*kC],  g_wr_l[kC*kC];
__device__ __nv_bfloat16 g_wo_h[kC*kC],  g_wo_l[kC*kC];
__device__ __nv_bfloat16 g_fk_h[kC*kHID], g_fk_l[kC*kHID];   // fWk^T [3072,768]
__device__ __nv_bfloat16 g_fv_h[kC*kHID], g_fv_l[kC*kHID];   // fWv^T [768,3072]
__device__ __nv_bfloat16 g_fr_h[kC*kC],  g_fr_l[kC*kC];

// ---------------- helpers ----------------
__device__ __forceinline__ uint32_t smem_u32(const void* p) {
    uint32_t a;
    asm("{ .reg .u64 t; cvta.to.shared.u64 t, %1; cvt.u32.u64 %0, t; }" : "=r"(a) : "l"(p));
    return a;
}
__device__ __forceinline__ uint32_t swz(uint32_t b) { return b ^ ((b >> 3) & 0x70); }

__device__ __forceinline__ void split2(float x, __nv_bfloat16& h, __nv_bfloat16& l) {
    h = __float2bfloat16(x);
    l = __float2bfloat16(x - __bfloat162float(h));
}

#define CP_ASYNC16(dst, src) \
    asm volatile("cp.async.cg.shared.global [%0], [%1], 16;" :: "r"(dst), "l"(src))
#define CP_COMMIT() asm volatile("cp.async.commit_group;" ::: "memory")
#define CP_WAIT0()  asm volatile("cp.async.wait_group 0;" ::: "memory")
#define CP_WAIT1()  asm volatile("cp.async.wait_group 1;" ::: "memory")

__device__ __forceinline__ void ldsm4(uint32_t& r0, uint32_t& r1, uint32_t& r2, uint32_t& r3, uint32_t addr) {
    asm volatile("ldmatrix.sync.aligned.m8n8.x4.shared.b16 {%0,%1,%2,%3}, [%4];"
                 : "=r"(r0), "=r"(r1), "=r"(r2), "=r"(r3) : "r"(addr));
}
__device__ __forceinline__ void mma16816(float* c, const uint32_t* a, const uint32_t* b) {
    asm volatile(
        "mma.sync.aligned.m16n8k16.row.col.f32.bf16.bf16.f32 "
        "{%0,%1,%2,%3}, {%4,%5,%6,%7}, {%8,%9}, {%0,%1,%2,%3};"
        : "+f"(c[0]), "+f"(c[1]), "+f"(c[2]), "+f"(c[3])
        : "r"(a[0]), "r"(a[1]), "r"(a[2]), "r"(a[3]), "r"(b[0]), "r"(b[1]));
}

// ---------------- HMMA GEMM, bf16 hi/lo split, 256x128 tile, 2-stage pipeline ----------------
// C[N x M] = A[N x K] * W^T (W^T stored [M x K]); block = 256 rows x 128 cols, warp = 64x64
// EPI: 0 none, 1 sigmoid, 2 relu^2, 3 res + s*acc, 4 res + acc
constexpr int kSAH = 0;             // A hi: 256 rows x 128B = 32KB
constexpr int kSAL = 32768;         // A lo: 32KB
constexpr int kSBH = 65536;         // B hi: 128 rows x 128B = 16KB
constexpr int kSBL = 81920;         // B lo: 16KB
constexpr int kStageB = 98304;      // 96KB per stage
template <int EPI>
__global__ void __launch_bounds__(256, 1)
hmma_gemm(const __nv_bfloat16* __restrict__ Ah, const __nv_bfloat16* __restrict__ Al,
          const __nv_bfloat16* __restrict__ Bh, const __nv_bfloat16* __restrict__ Bl,
          float* __restrict__ Cm, int K, int M,
          const float* __restrict__ res, const float* __restrict__ sg) {
    extern __shared__ char smem[];
    const uint32_t sb = smem_u32(smem);
    const int t = threadIdx.x, lane = t & 31, wid = t >> 5;
    const int rowBase = blockIdx.y * 256;
    const int colBase = blockIdx.x * 128;
    // warp tile: 64 rows x 64 cols
    const int mW = (wid & 3) * 64;
    const int nW = (wid >> 2) * 64;

    float acc[4][8][4];
    #pragma unroll
    for (int i = 0; i < 4; i++)
        #pragma unroll
        for (int j = 0; j < 8; j++)
            #pragma unroll
            for (int q = 0; q < 4; q++) acc[i][j][q] = 0.f;

    // global->smem: A: thread t loads full 128B of row t (8x16B per plane)
    //               B: thread t loads half 128B of row t>>1 (4x16B per plane)
    const __nv_bfloat16* gAh = Ah + (size_t)(rowBase + t) * K;
    const __nv_bfloat16* gAl = Al + (size_t)(rowBase + t) * K;
    const int bRow = t >> 1, bHalf = t & 1;
    const __nv_bfloat16* gBh = Bh + (size_t)(colBase + bRow) * K + bHalf * 32;
    const __nv_bfloat16* gBl = Bl + (size_t)(colBase + bRow) * K + bHalf * 32;
    uint32_t dstA[8], dstB[4];
    #pragma unroll
    for (int i = 0; i < 8; i++) dstA[i] = swz(t * 128 + i * 16);
    #pragma unroll
    for (int i = 0; i < 4; i++) dstB[i] = swz(bRow * 128 + bHalf * 64 + i * 16);

    const int nchunk = K >> 6;

    auto issue = [&](int kt, int stg) {
        const int ko = kt * 64;
        const uint32_t so = sb + stg * kStageB;
        #pragma unroll
        for (int i = 0; i < 8; i++) {
            CP_ASYNC16(so + kSAH + dstA[i], gAh + ko + i * 8);
            CP_ASYNC16(so + kSAL + dstA[i], gAl + ko + i * 8);
        }
        #pragma unroll
        for (int i = 0; i < 4; i++) {
            CP_ASYNC16(so + kSBH + dstB[i], gBh + ko + i * 8);
            CP_ASYNC16(so + kSBL + dstB[i], gBl + ko + i * 8);
        }
        CP_COMMIT();
    };

    // ldmatrix per-lane coords
    const int rA = lane & 15;
    const int kA = (lane >> 4) * 16;
    const int rB = (lane & 7) + ((lane >> 4) << 3);
    const int kB2 = ((lane >> 3) & 1) * 16;

    issue(0, 0);
    for (int kt = 0; kt < nchunk; ++kt) {
        const int cur = kt & 1;
        if (kt + 1 < nchunk) { issue(kt + 1, cur ^ 1); CP_WAIT1(); }
        else                 { CP_WAIT0(); }
        __syncthreads();
        const uint32_t so = sb + cur * kStageB;

        #pragma unroll
        for (int ks = 0; ks < 4; ++ks) {
            const int kbA = ks * 32 + kA;
            const int kbB = ks * 32 + kB2;
            uint32_t ah[4][4], al[4][4];
            #pragma unroll
            for (int mt = 0; mt < 4; mt++) {
                uint32_t off = swz((mW + mt * 16 + rA) * 128 + kbA);
                ldsm4(ah[mt][0], ah[mt][1], ah[mt][2], ah[mt][3], so + kSAH + off);
                ldsm4(al[mt][0], al[mt][1], al[mt][2], al[mt][3], so + kSAL + off);
            }
            uint32_t bh[8][2], bl[8][2];
            #pragma unroll
            for (int p = 0; p < 4; p++) {
                uint32_t off = swz((nW + p * 16 + rB) * 128 + kbB);
                ldsm4(bh[2 * p][0], bh[2 * p][1], bh[2 * p + 1][0], bh[2 * p + 1][1], so + kSBH + off);
                ldsm4(bl[2 * p][0], bl[2 * p][1], bl[2 * p + 1][0], bl[2 * p + 1][1], so + kSBL + off);
            }
            #pragma unroll
            for (int mt = 0; mt < 4; mt++)
                #pragma unroll
                for (int nt = 0; nt < 8; nt++) {
                    mma16816(acc[mt][nt], ah[mt], bh[nt]);
                    mma16816(acc[mt][nt], ah[mt], bl[nt]);
                    mma16816(acc[mt][nt], al[mt], bh[nt]);
                }
        }
        __syncthreads();
    }

    // epilogue
    #pragma unroll
    for (int mt = 0; mt < 4; mt++) {
        const int r = rowBase + mW + mt * 16 + (lane >> 2);
        #pragma unroll
        for (int half = 0; half < 2; half++) {
            const int rr = r + half * 8;
            const size_t gb = (size_t)rr * M + colBase + nW + (lane & 3) * 2;
            #pragma unroll
            for (int nt = 0; nt < 8; nt++) {
                float2 v = make_float2(acc[mt][nt][half * 2], acc[mt][nt][half * 2 + 1]);
                const size_t o = gb + nt * 8;
                if (EPI == 1) {
                    v.x = 1.f / (1.f + expf(-v.x));
                    v.y = 1.f / (1.f + expf(-v.y));
                } else if (EPI == 2) {
                    v.x = fmaxf(v.x, 0.f); v.x *= v.x;
                    v.y = fmaxf(v.y, 0.f); v.y *= v.y;
                } else if (EPI == 3) {
                    float2 r2 = *(const float2*)&res[o];
                    float2 s2 = *(const float2*)&sg[o];
                    v.x = r2.x + s2.x * v.x;
                    v.y = r2.y + s2.y * v.y;
                } else if (EPI == 4) {
                    float2 r2 = *(const float2*)&res[o];
                    v.x += r2.x; v.y += r2.y;
                }
                *(float2*)&Cm[o] = v;
            }
        }
    }
}

// ---------------- weight transpose + split ----------------
__global__ void wsplitT(const float* __restrict__ W, __nv_bfloat16* __restrict__ hi,
                        __nv_bfloat16* __restrict__ lo, int K, int M) {
    __shared__ float tile[32][33];
    int m0 = blockIdx.x * 32, k0 = blockIdx.y * 32;
    int tx = threadIdx.x, ty = threadIdx.y;
    #pragma unroll
    for (int r = 0; r < 32; r += 8)
        tile[ty + r][tx] = W[(size_t)(k0 + ty + r) * M + m0 + tx];
    __syncthreads();
    #pragma unroll
    for (int r = 0; r < 32; r += 8) {
        float v = tile[tx][ty + r];
        __nv_bfloat16 h, l;
        split2(v, h, l);
        size_t o = (size_t)(m0 + ty + r) * K + k0 + tx;
        hi[o] = h; lo[o] = l;
    }
}

// ---------------- block-wide mean/rstd (blockDim.x == 256) ----------------
__device__ __forceinline__ void block_stats(float s, float s2, float& mean, float& rstd, float invL) {
    #pragma unroll
    for (int o = 16; o; o >>= 1) {
        s  += __shfl_xor_sync(0xffffffffu, s,  o);
        s2 += __shfl_xor_sync(0xffffffffu, s2, o);
    }
    __shared__ float sh[16];
    int lane = threadIdx.x & 31, w = threadIdx.x >> 5;
    if (lane == 0) { sh[w] = s; sh[8 + w] = s2; }
    __syncthreads();
    if (threadIdx.x == 0) {
        float ts = 0.f, ts2 = 0.f;
        #pragma unroll
        for (int i = 0; i < 8; i++) { ts += sh[i]; ts2 += sh[8 + i]; }
        float m = ts * invL;
        float var = ts2 * invL - m * m;
        sh[0] = m;
        sh[1] = rsqrtf(var + kEPS);
    }
    __syncthreads();
    mean = sh[0]; rstd = sh[1];
    __syncthreads();
}

// ---------------- ln0 -> x0, ln1(x0) -> xi ----------------
__global__ void ln0ln1_kernel(const float* __restrict__ x,
                              const float* __restrict__ g0, const float* __restrict__ b0,
                              const float* __restrict__ g1, const float* __restrict__ b1,
                              float* __restrict__ x0, float* __restrict__ xi) {
    int row = blockIdx.x, tid = threadIdx.x;
    const float* p = x + (size_t)row * kC;
    float v[3], s = 0.f, s2 = 0.f;
    #pragma unroll
    for (int i = 0; i < 3; i++) { v[i] = p[tid + i * 256]; s += v[i]; s2 += v[i] * v[i]; }
    float m, rs;
    block_stats(s, s2, m, rs, 1.f / kC);
    float y[3];
    s = 0.f; s2 = 0.f;
    #pragma unroll
    for (int i = 0; i < 3; i++) {
        int c = tid + i * 256;
        y[i] = (v[i] - m) * rs * g0[c] + b0[c];
        x0[(size_t)row * kC + c] = y[i];
        s += y[i]; s2 += y[i] * y[i];
    }
    block_stats(s, s2, m, rs, 1.f / kC);
    #pragma unroll
    for (int i = 0; i < 3; i++) {
        int c = tid + i * 256;
        xi[(size_t)row * kC + c] = (y[i] - m) * rs * g1[c] + b1[c];
    }
}

// ---------------- generic LN; OUTP=true -> bf16 hi/lo planes (optional *sMul) ----------------
template <int L, bool OUTP>
__global__ void ln_kernel(const float* __restrict__ in, const float* __restrict__ g,
                          const float* __restrict__ b, const float* __restrict__ sMul,
                          float* __restrict__ outF,
                          __nv_bfloat16* __restrict__ outH, __nv_bfloat16* __restrict__ outL) {
    constexpr int PT = L / 256;
    int row = blockIdx.x, tid = threadIdx.x;
    const float* p = in + (size_t)row * L;
    float v[PT], s = 0.f, s2 = 0.f;
    #pragma unroll
    for (int i = 0; i < PT; i++) { v[i] = p[tid + i * 256]; s += v[i]; s2 += v[i] * v[i]; }
    float m, rs;
    block_stats(s, s2, m, rs, 1.f / L);
    #pragma unroll
    for (int i = 0; i < PT; i++) {
        int c = tid + i * 256;
        size_t o = (size_t)row * L + c;
        float y = (v[i] - m) * rs * g[c] + b[c];
        if (sMul != nullptr) y *= sMul[o];
        if (OUTP) {
            __nv_bfloat16 h, l;
            split2(y, h, l);
            outH[o] = h; outL[o] = l;
        } else {
            outF[o] = y;
        }
    }
}

// ---------------- q_shift + token mixes -> bf16 planes ----------------
template <bool HASV>
__global__ void shiftmix_kernel(const float* __restrict__ xi,
                                const float* __restrict__ mk, const float* __restrict__ mv,
                                const float* __restrict__ mr,
                                __nv_bfloat16* __restrict__ kh, __nv_bfloat16* __restrict__ kl,
                                __nv_bfloat16* __restrict__ vh, __nv_bfloat16* __restrict__ vl,
                                __nv_bfloat16* __restrict__ rh, __nv_bfloat16* __restrict__ rl) {
    int idx = blockIdx.x * 256 + threadIdx.x;
    if (idx >= kNC) return;
    int c = idx % kC;
    int n = idx / kC;
    int t = n % kT;
    int h = t / kW;
    int w = t % kW;
    int grp = c / (kC / 4);
    int hh = h, ww = w;
    bool ok;
    if (grp == 0)      { ww = w - 1; ok = (ww >= 0);  }
    else if (grp == 1) { ww = w + 1; ok = (ww < kW);  }
    else if (grp == 2) { hh = h - 1; ok = (hh >= 0);  }
    else               { hh = h + 1; ok = (hh < kH);  }
    float xx = 0.f;
    float xiv = xi[idx];
    if (ok) {
        int n2 = (n - t) + hh * kW + ww;
        xx = xi[(size_t)n2 * kC + c];
    }
    __nv_bfloat16 hB, lB;
    float a = mk[c];
    split2(xiv * a + xx * (1.f - a), hB, lB); kh[idx] = hB; kl[idx] = lB;
    if (HASV) {
        a = mv[c];
        split2(xiv * a + xx * (1.f - a), hB, lB); vh[idx] = hB; vl[idx] = lB;
    }
    a = mr[c];
    split2(xiv * a + xx * (1.f - a), hB, lB); rh[idx] = hB; rl[idx] = lB;
}

// ---------------- bidirectional WKV ----------------
__global__ void wkv_kernel(const float* __restrict__ k, const float* __restrict__ v,
                           const float* __restrict__ decay, const float* __restrict__ first,
                           float* __restrict__ tA, float* __restrict__ tB,
                           float* __restrict__ out) {
    int idx = blockIdx.x * 256 + threadIdx.x;
    if (idx >= kBC) return;
    int b = idx / kC;
    int c = idx % kC;
    float wv = decay[c] * (1.f / kT);
    float u  = first[c] * (1.f / kT);
    float d  = expf(-wv);
    float ew = expf(wv);
    size_t base = (size_t)b * kT * kC + c;

    float kmax = -3.4e38f;
    for (int t = 0; t < kT; t++) kmax = fmaxf(kmax, k[base + (size_t)t * kC]);

    float a = 0.f, bb = 0.f;
    for (int t = kT - 1; t >= 0; --t) {
        size_t o = base + (size_t)t * kC;
        tA[o] = a; tB[o] = bb;
        float ek = expf(k[o] - kmax);
        a  = d * (a  + ek * v[o]);
        bb = d * (bb + ek);
    }
    a = 0.f; bb = 0.f;
    for (int t = 0; t < kT; t++) {
        size_t o = base + (size_t)t * kC;
        float kk = k[o];
        float vv = v[o];
        float ek = expf(kk - kmax);
        float eu = expf(u + kk - kmax);
        float num = ew * (a  + tA[o]) + eu * vv;
        float den = ew * (bb + tB[o]) + eu;
        out[o] = num / den;
        a  = d * (a  + ek * vv);
        bb = d * (bb + ek);
    }
}

// ---------------- launch ----------------
extern "C" void kernel_launch(void* const* d_in, const int* in_sizes, int n_in,
                              void* d_out, int out_size) {
    const float* x      = (const float*)d_in[0];
    const float* ln0_g  = (const float*)d_in[1];
    const float* ln0_b  = (const float*)d_in[2];
    const float* ln1_g  = (const float*)d_in[3];
    const float* ln1_b  = (const float*)d_in[4];
    const float* ln2_g  = (const float*)d_in[5];
    const float* ln2_b  = (const float*)d_in[6];
    const float* amk    = (const float*)d_in[7];
    const float* amv    = (const float*)d_in[8];
    const float* amr    = (const float*)d_in[9];
    const float* adecay = (const float*)d_in[10];
    const float* afirst = (const float*)d_in[11];
    const float* Wk     = (const float*)d_in[12];
    const float* Wv     = (const float*)d_in[13];
    const float* Wr     = (const float*)d_in[14];
    const float* Wo     = (const float*)d_in[15];
    const float* akn_g  = (const float*)d_in[16];
    const float* akn_b  = (const float*)d_in[17];
    const float* fmk    = (const float*)d_in[18];
    const float* fmr    = (const float*)d_in[19];
    const float* fWk    = (const float*)d_in[20];
    const float* fWv    = (const float*)d_in[21];
    const float* fWr    = (const float*)d_in[22];
    const float* fkn_g  = (const float*)d_in[23];
    const float* fkn_b  = (const float*)d_in[24];
    float* out = (float*)d_out;

    float *px0, *pxi, *pk, *pv, *psr, *ptA, *ptB, *prw, *phid;
    cudaGetSymbolAddress((void**)&px0,  g_x0);
    cudaGetSymbolAddress((void**)&pxi,  g_xi);
    cudaGetSymbolAddress((void**)&pk,   g_k);
    cudaGetSymbolAddress((void**)&pv,   g_v);
    cudaGetSymbolAddress((void**)&psr,  g_sr);
    cudaGetSymbolAddress((void**)&ptA,  g_tA);
    cudaGetSymbolAddress((void**)&ptB,  g_tB);
    cudaGetSymbolAddress((void**)&prw,  g_rw);
    cudaGetSymbolAddress((void**)&phid, g_hid);

    __nv_bfloat16 *akh, *akl, *avh, *avl, *arh, *arl, *hh, *hl;
    cudaGetSymbolAddress((void**)&akh, g_ak_h); cudaGetSymbolAddress((void**)&akl, g_ak_l);
    cudaGetSymbolAddress((void**)&avh, g_av_h); cudaGetSymbolAddress((void**)&avl, g_av_l);
    cudaGetSymbolAddress((void**)&arh, g_ar_h); cudaGetSymbolAddress((void**)&arl, g_ar_l);
    cudaGetSymbolAddress((void**)&hh,  g_hh);   cudaGetSymbolAddress((void**)&hl,  g_hl);

    __nv_bfloat16 *wkh, *wkl, *wvh, *wvl, *wrh, *wrl, *woh, *wol, *fkh, *fkl, *fvh, *fvl, *frh, *frl;
    cudaGetSymbolAddress((void**)&wkh, g_wk_h); cudaGetSymbolAddress((void**)&wkl, g_wk_l);
    cudaGetSymbolAddress((void**)&wvh, g_wv_h); cudaGetSymbolAddress((void**)&wvl, g_wv_l);
    cudaGetSymbolAddress((void**)&wrh, g_wr_h); cudaGetSymbolAddress((void**)&wrl, g_wr_l);
    cudaGetSymbolAddress((void**)&woh, g_wo_h); cudaGetSymbolAddress((void**)&wol, g_wo_l);
    cudaGetSymbolAddress((void**)&fkh, g_fk_h); cudaGetSymbolAddress((void**)&fkl, g_fk_l);
    cudaGetSymbolAddress((void**)&fvh, g_fv_h); cudaGetSymbolAddress((void**)&fvl, g_fv_l);
    cudaGetSymbolAddress((void**)&frh, g_fr_h); cudaGetSymbolAddress((void**)&frl, g_fr_l);

    constexpr int kSmem = 2 * kStageB;   // 192 KB
    cudaFuncSetAttribute(hmma_gemm<0>, cudaFuncAttributeMaxDynamicSharedMemorySize, kSmem);
    cudaFuncSetAttribute(hmma_gemm<1>, cudaFuncAttributeMaxDynamicSharedMemorySize, kSmem);
    cudaFuncSetAttribute(hmma_gemm<2>, cudaFuncAttributeMaxDynamicSharedMemorySize, kSmem);
    cudaFuncSetAttribute(hmma_gemm<3>, cudaFuncAttributeMaxDynamicSharedMemorySize, kSmem);
    cudaFuncSetAttribute(hmma_gemm<4>, cudaFuncAttributeMaxDynamicSharedMemorySize, kSmem);

    const dim3 tb(32, 8);
    const dim3 gCC(kC / 32, kC / 32);
    wsplitT<<<gCC, tb>>>(Wk,  wkh, wkl, kC, kC);
    wsplitT<<<gCC, tb>>>(Wv,  wvh, wvl, kC, kC);
    wsplitT<<<gCC, tb>>>(Wr,  wrh, wrl, kC, kC);
    wsplitT<<<gCC, tb>>>(Wo,  woh, wol, kC, kC);
    wsplitT<<<dim3(kHID / 32, kC / 32), tb>>>(fWk, fkh, fkl, kC, kHID);   // [3072,768]
    wsplitT<<<dim3(kC / 32, kHID / 32), tb>>>(fWv, fvh, fvl, kHID, kC);   // [768,3072]
    wsplitT<<<gCC, tb>>>(fWr, frh, frl, kC, kC);

    const dim3 gC(kC / 128, kN / 256);     // (6, 98)
    const dim3 gH(kHID / 128, kN / 256);   // (24, 98)

    // --- attention branch ---
    ln0ln1_kernel<<<kN, 256>>>(x, ln0_g, ln0_b, ln1_g, ln1_b, px0, pxi);
    shiftmix_kernel<true><<<kNC / 256, 256>>>(pxi, amk, amv, amr, akh, akl, avh, avl, arh, arl);
    hmma_gemm<0><<<gC, 256, kSmem>>>(akh, akl, wkh, wkl, pk,  kC, kC, nullptr, nullptr);
    hmma_gemm<0><<<gC, 256, kSmem>>>(avh, avl, wvh, wvl, pv,  kC, kC, nullptr, nullptr);
    hmma_gemm<1><<<gC, 256, kSmem>>>(arh, arl, wrh, wrl, psr, kC, kC, nullptr, nullptr);
    wkv_kernel<<<kBC / 256, 256>>>(pk, pv, adecay, afirst, ptA, ptB, prw);
    // (sr * LN(rwkv)) -> planes (reuse av planes); sr multiplies BEFORE Wo
    ln_kernel<kC, true><<<kN, 256>>>(prw, akn_g, akn_b, psr, nullptr, avh, avl);
    hmma_gemm<4><<<gC, 256, kSmem>>>(avh, avl, woh, wol, px0, kC, kC, px0, nullptr);

    // --- FFN branch ---
    ln_kernel<kC, false><<<kN, 256>>>(px0, ln2_g, ln2_b, nullptr, pxi, nullptr, nullptr);
    shiftmix_kernel<false><<<kNC / 256, 256>>>(pxi, fmk, nullptr, fmr, akh, akl, nullptr, nullptr, arh, arl);
    hmma_gemm<2><<<gH, 256, kSmem>>>(akh, akl, fkh, fkl, phid, kC, kHID, nullptr, nullptr);  // relu^2
    ln_kernel<kHID, true><<<kN, 256>>>(phid, fkn_g, fkn_b, nullptr, nullptr, hh, hl);
    hmma_gemm<1><<<gC, 256, kSmem>>>(arh, arl, frh, frl, psr, kC, kC, nullptr, nullptr);     // sigmoid gate
    hmma_gemm<3><<<gC, 256, kSmem>>>(hh, hl, fvh, fvl, out, kHID, kC, px0, psr);             // out = x0 + gate*kv
}

// round 11
// speedup vs baseline: 1.0750x; 1.0750x over previous
#include <cuda_runtime.h>
#include <cuda_bf16.h>
#include <math.h>
#include <stdint.h>

// ---------------- constants ----------------
constexpr int kB   = 128;
constexpr int kT   = 196;
constexpr int kC   = 768;
constexpr int kHID = 3072;
constexpr int kH   = 14;
constexpr int kW   = 14;
constexpr int kN   = kB * kT;        // 25088 rows
constexpr int kNC  = kN * kC;
constexpr int kNH  = kN * kHID;
constexpr int kBC  = kB * kC;
constexpr float kEPS = 1e-5f;

// ---------------- scratch (device globals) ----------------
__device__ float g_x0[kNC];
__device__ float g_xi[kNC];
__device__ float g_k [kNC];
__device__ float g_v [kNC];
__device__ float g_sr[kNC];
__device__ float g_tA[kNC];
__device__ float g_tB[kNC];
__device__ float g_rw[kNC];
__device__ float g_hid[kNH];
// bf16 activation planes (hi/lo)
__device__ __nv_bfloat16 g_ak_h[kNC], g_ak_l[kNC];
__device__ __nv_bfloat16 g_av_h[kNC], g_av_l[kNC];
__device__ __nv_bfloat16 g_ar_h[kNC], g_ar_l[kNC];
__device__ __nv_bfloat16 g_hh  [kNH], g_hl  [kNH];
// bf16 transposed weight planes [Mout, K]
__device__ __nv_bfloat16 g_wk_h[kC*kC],  g_wk_l[kC*kC];
__device__ __nv_bfloat16 g_wv_h[kC*kC],  g_wv_l[kC*kC];
__device__ __nv_bfloat16 g_wr_h[kC*kC],  g_wr_l[kC*kC];
__device__ __nv_bfloat16 g_wo_h[kC*kC],  g_wo_l[kC*kC];
__device__ __nv_bfloat16 g_fk_h[kC*kHID], g_fk_l[kC*kHID];   // fWk^T [3072,768]
__device__ __nv_bfloat16 g_fv_h[kC*kHID], g_fv_l[kC*kHID];   // fWv^T [768,3072]
__device__ __nv_bfloat16 g_fr_h[kC*kC],  g_fr_l[kC*kC];

// ---------------- helpers ----------------
__device__ __forceinline__ uint32_t smem_u32(const void* p) {
    uint32_t a;
    asm("{ .reg .u64 t; cvta.to.shared.u64 t, %1; cvt.u32.u64 %0, t; }" : "=r"(a) : "l"(p));
    return a;
}
__device__ __forceinline__ uint32_t swz(uint32_t b) { return b ^ ((b >> 3) & 0x70); }

__device__ __forceinline__ void split2(float x, __nv_bfloat16& h, __nv_bfloat16& l) {
    h = __float2bfloat16(x);
    l = __float2bfloat16(x - __bfloat162float(h));
}

#define CP_ASYNC16(dst, src) \
    asm volatile("cp.async.cg.shared.global [%0], [%1], 16;" :: "r"(dst), "l"(src))
#define CP_COMMIT() asm volatile("cp.async.commit_group;" ::: "memory")
#define CP_WAIT0()  asm volatile("cp.async.wait_group 0;" ::: "memory")
#define CP_WAIT1()  asm volatile("cp.async.wait_group 1;" ::: "memory")
#define CP_WAIT2()  asm volatile("cp.async.wait_group 2;" ::: "memory")

__device__ __forceinline__ void ldsm4(uint32_t& r0, uint32_t& r1, uint32_t& r2, uint32_t& r3, uint32_t addr) {
    asm volatile("ldmatrix.sync.aligned.m8n8.x4.shared.b16 {%0,%1,%2,%3}, [%4];"
                 : "=r"(r0), "=r"(r1), "=r"(r2), "=r"(r3) : "r"(addr));
}
__device__ __forceinline__ void mma16816(float* c, const uint32_t* a, const uint32_t* b) {
    asm volatile(
        "mma.sync.aligned.m16n8k16.row.col.f32.bf16.bf16.f32 "
        "{%0,%1,%2,%3}, {%4,%5,%6,%7}, {%8,%9}, {%0,%1,%2,%3};"
        : "+f"(c[0]), "+f"(c[1]), "+f"(c[2]), "+f"(c[3])
        : "r"(a[0]), "r"(a[1]), "r"(a[2]), "r"(a[3]), "r"(b[0]), "r"(b[1]));
}

// ---------------- HMMA GEMM, bf16 hi/lo split, 128x128 tile, 3-stage pipeline ----------------
// C[N x M] = A[N x K] * W^T (W^T stored [M x K]); warp tile 64x32
// EPI: 0 none, 1 sigmoid, 2 relu^2, 3 res + s*acc, 4 res + acc
constexpr int kStageB = 64 * 1024;   // 4 planes x 16KB
constexpr int kNStage = 3;
template <int EPI>
__global__ void __launch_bounds__(256, 1)
hmma_gemm(const __nv_bfloat16* __restrict__ Ah, const __nv_bfloat16* __restrict__ Al,
          const __nv_bfloat16* __restrict__ Bh, const __nv_bfloat16* __restrict__ Bl,
          float* __restrict__ Cm, int K, int M,
          const float* __restrict__ res, const float* __restrict__ sg) {
    extern __shared__ char smem[];
    const uint32_t sb = smem_u32(smem);
    const int t = threadIdx.x, lane = t & 31, wid = t >> 5;
    const int rowBase = blockIdx.y * 128;
    const int colBase = blockIdx.x * 128;
    // warp tile: 64 rows x 32 cols
    const int mW = (wid & 1) * 64;
    const int nW = (wid >> 1) * 32;
    constexpr int SAH = 0, SAL = 16384, SBH = 32768, SBL = 49152;

    float acc[4][4][4];
    #pragma unroll
    for (int i = 0; i < 4; i++)
        #pragma unroll
        for (int j = 0; j < 4; j++)
            #pragma unroll
            for (int q = 0; q < 4; q++) acc[i][j][q] = 0.f;

    // global->smem: thread t loads half a 128B row (4x16B) of each plane
    const int lrow = t >> 1, lhalf = t & 1;
    const __nv_bfloat16* gAh = Ah + (size_t)(rowBase + lrow) * K + lhalf * 32;
    const __nv_bfloat16* gAl = Al + (size_t)(rowBase + lrow) * K + lhalf * 32;
    const __nv_bfloat16* gBh = Bh + (size_t)(colBase + lrow) * K + lhalf * 32;
    const __nv_bfloat16* gBl = Bl + (size_t)(colBase + lrow) * K + lhalf * 32;
    uint32_t dst[4];
    #pragma unroll
    for (int i = 0; i < 4; i++) dst[i] = swz(lrow * 128 + lhalf * 64 + i * 16);

    const int nchunk = K >> 6;

    auto issue = [&](int kt) {
        const int ko = kt * 64;
        const uint32_t so = sb + (kt % kNStage) * kStageB;
        #pragma unroll
        for (int i = 0; i < 4; i++) {
            CP_ASYNC16(so + SAH + dst[i], gAh + ko + i * 8);
            CP_ASYNC16(so + SAL + dst[i], gAl + ko + i * 8);
            CP_ASYNC16(so + SBH + dst[i], gBh + ko + i * 8);
            CP_ASYNC16(so + SBL + dst[i], gBl + ko + i * 8);
        }
        CP_COMMIT();
    };

    // ldmatrix per-lane coords
    const int rA = lane & 15;
    const int kA = (lane >> 4) * 16;
    const int rB = (lane & 7) + ((lane >> 4) << 3);
    const int kB2 = ((lane >> 3) & 1) * 16;

    issue(0);
    if (nchunk > 1) issue(1);
    for (int kt = 0; kt < nchunk; ++kt) {
        if (kt + 2 < nchunk) issue(kt + 2);
        const int newer = nchunk - 1 - kt < 2 ? nchunk - 1 - kt : 2;
        if (newer == 2)      CP_WAIT2();
        else if (newer == 1) CP_WAIT1();
        else                 CP_WAIT0();
        __syncthreads();
        const uint32_t so = sb + (kt % kNStage) * kStageB;

        #pragma unroll
        for (int ks = 0; ks < 4; ++ks) {
            const int kbA = ks * 32 + kA;
            const int kbB = ks * 32 + kB2;
            uint32_t ah[4][4], al[4][4];
            #pragma unroll
            for (int mt = 0; mt < 4; mt++) {
                uint32_t off = swz((mW + mt * 16 + rA) * 128 + kbA);
                ldsm4(ah[mt][0], ah[mt][1], ah[mt][2], ah[mt][3], so + SAH + off);
                ldsm4(al[mt][0], al[mt][1], al[mt][2], al[mt][3], so + SAL + off);
            }
            uint32_t bh[4][2], bl[4][2];
            #pragma unroll
            for (int p = 0; p < 2; p++) {
                uint32_t off = swz((nW + p * 16 + rB) * 128 + kbB);
                ldsm4(bh[2 * p][0], bh[2 * p][1], bh[2 * p + 1][0], bh[2 * p + 1][1], so + SBH + off);
                ldsm4(bl[2 * p][0], bl[2 * p][1], bl[2 * p + 1][0], bl[2 * p + 1][1], so + SBL + off);
            }
            // term-separated passes: 16 independent MMAs per pass (no
            // back-to-back same-accumulator dependencies)
            #pragma unroll
            for (int mt = 0; mt < 4; mt++)
                #pragma unroll
                for (int nt = 0; nt < 4; nt++)
                    mma16816(acc[mt][nt], ah[mt], bh[nt]);
            #pragma unroll
            for (int mt = 0; mt < 4; mt++)
                #pragma unroll
                for (int nt = 0; nt < 4; nt++)
                    mma16816(acc[mt][nt], ah[mt], bl[nt]);
            #pragma unroll
            for (int mt = 0; mt < 4; mt++)
                #pragma unroll
                for (int nt = 0; nt < 4; nt++)
                    mma16816(acc[mt][nt], al[mt], bh[nt]);
        }
        __syncthreads();
    }

    // epilogue
    #pragma unroll
    for (int mt = 0; mt < 4; mt++) {
        const int r = rowBase + mW + mt * 16 + (lane >> 2);
        #pragma unroll
        for (int half = 0; half < 2; half++) {
            const int rr = r + half * 8;
            const size_t gb = (size_t)rr * M + colBase + nW + (lane & 3) * 2;
            #pragma unroll
            for (int nt = 0; nt < 4; nt++) {
                float2 v = make_float2(acc[mt][nt][half * 2], acc[mt][nt][half * 2 + 1]);
                const size_t o = gb + nt * 8;
                if (EPI == 1) {
                    v.x = 1.f / (1.f + expf(-v.x));
                    v.y = 1.f / (1.f + expf(-v.y));
                } else if (EPI == 2) {
                    v.x = fmaxf(v.x, 0.f); v.x *= v.x;
                    v.y = fmaxf(v.y, 0.f); v.y *= v.y;
                } else if (EPI == 3) {
                    float2 r2 = *(const float2*)&res[o];
                    float2 s2 = *(const float2*)&sg[o];
                    v.x = r2.x + s2.x * v.x;
                    v.y = r2.y + s2.y * v.y;
                } else if (EPI == 4) {
                    float2 r2 = *(const float2*)&res[o];
                    v.x += r2.x; v.y += r2.y;
                }
                *(float2*)&Cm[o] = v;
            }
        }
    }
}

// ---------------- weight transpose + split ----------------
__global__ void wsplitT(const float* __restrict__ W, __nv_bfloat16* __restrict__ hi,
                        __nv_bfloat16* __restrict__ lo, int K, int M) {
    __shared__ float tile[32][33];
    int m0 = blockIdx.x * 32, k0 = blockIdx.y * 32;
    int tx = threadIdx.x, ty = threadIdx.y;
    #pragma unroll
    for (int r = 0; r < 32; r += 8)
        tile[ty + r][tx] = W[(size_t)(k0 + ty + r) * M + m0 + tx];
    __syncthreads();
    #pragma unroll
    for (int r = 0; r < 32; r += 8) {
        float v = tile[tx][ty + r];
        __nv_bfloat16 h, l;
        split2(v, h, l);
        size_t o = (size_t)(m0 + ty + r) * K + k0 + tx;
        hi[o] = h; lo[o] = l;
    }
}

// ---------------- block-wide mean/rstd (blockDim.x == 256) ----------------
__device__ __forceinline__ void block_stats(float s, float s2, float& mean, float& rstd, float invL) {
    #pragma unroll
    for (int o = 16; o; o >>= 1) {
        s  += __shfl_xor_sync(0xffffffffu, s,  o);
        s2 += __shfl_xor_sync(0xffffffffu, s2, o);
    }
    __shared__ float sh[16];
    int lane = threadIdx.x & 31, w = threadIdx.x >> 5;
    if (lane == 0) { sh[w] = s; sh[8 + w] = s2; }
    __syncthreads();
    if (threadIdx.x == 0) {
        float ts = 0.f, ts2 = 0.f;
        #pragma unroll
        for (int i = 0; i < 8; i++) { ts += sh[i]; ts2 += sh[8 + i]; }
        float m = ts * invL;
        float var = ts2 * invL - m * m;
        sh[0] = m;
        sh[1] = rsqrtf(var + kEPS);
    }
    __syncthreads();
    mean = sh[0]; rstd = sh[1];
    __syncthreads();
}

// ---------------- ln0 -> x0, ln1(x0) -> xi ----------------
__global__ void ln0ln1_kernel(const float* __restrict__ x,
                              const float* __restrict__ g0, const float* __restrict__ b0,
                              const float* __restrict__ g1, const float* __restrict__ b1,
                              float* __restrict__ x0, float* __restrict__ xi) {
    int row = blockIdx.x, tid = threadIdx.x;
    const float* p = x + (size_t)row * kC;
    float v[3], s = 0.f, s2 = 0.f;
    #pragma unroll
    for (int i = 0; i < 3; i++) { v[i] = p[tid + i * 256]; s += v[i]; s2 += v[i] * v[i]; }
    float m, rs;
    block_stats(s, s2, m, rs, 1.f / kC);
    float y[3];
    s = 0.f; s2 = 0.f;
    #pragma unroll
    for (int i = 0; i < 3; i++) {
        int c = tid + i * 256;
        y[i] = (v[i] - m) * rs * g0[c] + b0[c];
        x0[(size_t)row * kC + c] = y[i];
        s += y[i]; s2 += y[i] * y[i];
    }
    block_stats(s, s2, m, rs, 1.f / kC);
    #pragma unroll
    for (int i = 0; i < 3; i++) {
        int c = tid + i * 256;
        xi[(size_t)row * kC + c] = (y[i] - m) * rs * g1[c] + b1[c];
    }
}

// ---------------- generic LN; OUTP=true -> bf16 hi/lo planes (optional *sMul) ----------------
template <int L, bool OUTP>
__global__ void ln_kernel(const float* __restrict__ in, const float* __restrict__ g,
                          const float* __restrict__ b, const float* __restrict__ sMul,
                          float* __restrict__ outF,
                          __nv_bfloat16* __restrict__ outH, __nv_bfloat16* __restrict__ outL) {
    constexpr int PT = L / 256;
    int row = blockIdx.x, tid = threadIdx.x;
    const float* p = in + (size_t)row * L;
    float v[PT], s = 0.f, s2 = 0.f;
    #pragma unroll
    for (int i = 0; i < PT; i++) { v[i] = p[tid + i * 256]; s += v[i]; s2 += v[i] * v[i]; }
    float m, rs;
    block_stats(s, s2, m, rs, 1.f / L);
    #pragma unroll
    for (int i = 0; i < PT; i++) {
        int c = tid + i * 256;
        size_t o = (size_t)row * L + c;
        float y = (v[i] - m) * rs * g[c] + b[c];
        if (sMul != nullptr) y *= sMul[o];
        if (OUTP) {
            __nv_bfloat16 h, l;
            split2(y, h, l);
            outH[o] = h; outL[o] = l;
        } else {
            outF[o] = y;
        }
    }
}

// ---------------- q_shift + token mixes -> bf16 planes ----------------
template <bool HASV>
__global__ void shiftmix_kernel(const float* __restrict__ xi,
                                const float* __restrict__ mk, const float* __restrict__ mv,
                                const float* __restrict__ mr,
                                __nv_bfloat16* __restrict__ kh, __nv_bfloat16* __restrict__ kl,
                                __nv_bfloat16* __restrict__ vh, __nv_bfloat16* __restrict__ vl,
                                __nv_bfloat16* __restrict__ rh, __nv_bfloat16* __restrict__ rl) {
    int idx = blockIdx.x * 256 + threadIdx.x;
    if (idx >= kNC) return;
    int c = idx % kC;
    int n = idx / kC;
    int t = n % kT;
    int h = t / kW;
    int w = t % kW;
    int grp = c / (kC / 4);
    int hh = h, ww = w;
    bool ok;
    if (grp == 0)      { ww = w - 1; ok = (ww >= 0);  }
    else if (grp == 1) { ww = w + 1; ok = (ww < kW);  }
    else if (grp == 2) { hh = h - 1; ok = (hh >= 0);  }
    else               { hh = h + 1; ok = (hh < kH);  }
    float xx = 0.f;
    float xiv = xi[idx];
    if (ok) {
        int n2 = (n - t) + hh * kW + ww;
        xx = xi[(size_t)n2 * kC + c];
    }
    __nv_bfloat16 hB, lB;
    float a = mk[c];
    split2(xiv * a + xx * (1.f - a), hB, lB); kh[idx] = hB; kl[idx] = lB;
    if (HASV) {
        a = mv[c];
        split2(xiv * a + xx * (1.f - a), hB, lB); vh[idx] = hB; vl[idx] = lB;
    }
    a = mr[c];
    split2(xiv * a + xx * (1.f - a), hB, lB); rh[idx] = hB; rl[idx] = lB;
}

// ---------------- bidirectional WKV ----------------
__global__ void wkv_kernel(const float* __restrict__ k, const float* __restrict__ v,
                           const float* __restrict__ decay, const float* __restrict__ first,
                           float* __restrict__ tA, float* __restrict__ tB,
                           float* __restrict__ out) {
    int idx = blockIdx.x * 256 + threadIdx.x;
    if (idx >= kBC) return;
    int b = idx / kC;
    int c = idx % kC;
    float wv = decay[c] * (1.f / kT);
    float u  = first[c] * (1.f / kT);
    float d  = expf(-wv);
    float ew = expf(wv);
    size_t base = (size_t)b * kT * kC + c;

    float kmax = -3.4e38f;
    for (int t = 0; t < kT; t++) kmax = fmaxf(kmax, k[base + (size_t)t * kC]);

    float a = 0.f, bb = 0.f;
    for (int t = kT - 1; t >= 0; --t) {
        size_t o = base + (size_t)t * kC;
        tA[o] = a; tB[o] = bb;
        float ek = expf(k[o] - kmax);
        a  = d * (a  + ek * v[o]);
        bb = d * (bb + ek);
    }
    a = 0.f; bb = 0.f;
    for (int t = 0; t < kT; t++) {
        size_t o = base + (size_t)t * kC;
        float kk = k[o];
        float vv = v[o];
        float ek = expf(kk - kmax);
        float eu = expf(u + kk - kmax);
        float num = ew * (a  + tA[o]) + eu * vv;
        float den = ew * (bb + tB[o]) + eu;
        out[o] = num / den;
        a  = d * (a  + ek * vv);
        bb = d * (bb + ek);
    }
}

// ---------------- launch ----------------
extern "C" void kernel_launch(void* const* d_in, const int* in_sizes, int n_in,
                              void* d_out, int out_size) {
    const float* x      = (const float*)d_in[0];
    const float* ln0_g  = (const float*)d_in[1];
    const float* ln0_b  = (const float*)d_in[2];
    const float* ln1_g  = (const float*)d_in[3];
    const float* ln1_b  = (const float*)d_in[4];
    const float* ln2_g  = (const float*)d_in[5];
    const float* ln2_b  = (const float*)d_in[6];
    const float* amk    = (const float*)d_in[7];
    const float* amv    = (const float*)d_in[8];
    const float* amr    = (const float*)d_in[9];
    const float* adecay = (const float*)d_in[10];
    const float* afirst = (const float*)d_in[11];
    const float* Wk     = (const float*)d_in[12];
    const float* Wv     = (const float*)d_in[13];
    const float* Wr     = (const float*)d_in[14];
    const float* Wo     = (const float*)d_in[15];
    const float* akn_g  = (const float*)d_in[16];
    const float* akn_b  = (const float*)d_in[17];
    const float* fmk    = (const float*)d_in[18];
    const float* fmr    = (const float*)d_in[19];
    const float* fWk    = (const float*)d_in[20];
    const float* fWv    = (const float*)d_in[21];
    const float* fWr    = (const float*)d_in[22];
    const float* fkn_g  = (const float*)d_in[23];
    const float* fkn_b  = (const float*)d_in[24];
    float* out = (float*)d_out;

    float *px0, *pxi, *pk, *pv, *psr, *ptA, *ptB, *prw, *phid;
    cudaGetSymbolAddress((void**)&px0,  g_x0);
    cudaGetSymbolAddress((void**)&pxi,  g_xi);
    cudaGetSymbolAddress((void**)&pk,   g_k);
    cudaGetSymbolAddress((void**)&pv,   g_v);
    cudaGetSymbolAddress((void**)&psr,  g_sr);
    cudaGetSymbolAddress((void**)&ptA,  g_tA);
    cudaGetSymbolAddress((void**)&ptB,  g_tB);
    cudaGetSymbolAddress((void**)&prw,  g_rw);
    cudaGetSymbolAddress((void**)&phid, g_hid);

    __nv_bfloat16 *akh, *akl, *avh, *avl, *arh, *arl, *hh, *hl;
    cudaGetSymbolAddress((void**)&akh, g_ak_h); cudaGetSymbolAddress((void**)&akl, g_ak_l);
    cudaGetSymbolAddress((void**)&avh, g_av_h); cudaGetSymbolAddress((void**)&avl, g_av_l);
    cudaGetSymbolAddress((void**)&arh, g_ar_h); cudaGetSymbolAddress((void**)&arl, g_ar_l);
    cudaGetSymbolAddress((void**)&hh,  g_hh);   cudaGetSymbolAddress((void**)&hl,  g_hl);

    __nv_bfloat16 *wkh, *wkl, *wvh, *wvl, *wrh, *wrl, *woh, *wol, *fkh, *fkl, *fvh, *fvl, *frh, *frl;
    cudaGetSymbolAddress((void**)&wkh, g_wk_h); cudaGetSymbolAddress((void**)&wkl, g_wk_l);
    cudaGetSymbolAddress((void**)&wvh, g_wv_h); cudaGetSymbolAddress((void**)&wvl, g_wv_l);
    cudaGetSymbolAddress((void**)&wrh, g_wr_h); cudaGetSymbolAddress((void**)&wrl, g_wr_l);
    cudaGetSymbolAddress((void**)&woh, g_wo_h); cudaGetSymbolAddress((void**)&wol, g_wo_l);
    cudaGetSymbolAddress((void**)&fkh, g_fk_h); cudaGetSymbolAddress((void**)&fkl, g_fk_l);
    cudaGetSymbolAddress((void**)&fvh, g_fv_h); cudaGetSymbolAddress((void**)&fvl, g_fv_l);
    cudaGetSymbolAddress((void**)&frh, g_fr_h); cudaGetSymbolAddress((void**)&frl, g_fr_l);

    constexpr int kSmem = kNStage * kStageB;   // 192 KB
    cudaFuncSetAttribute(hmma_gemm<0>, cudaFuncAttributeMaxDynamicSharedMemorySize, kSmem);
    cudaFuncSetAttribute(hmma_gemm<1>, cudaFuncAttributeMaxDynamicSharedMemorySize, kSmem);
    cudaFuncSetAttribute(hmma_gemm<2>, cudaFuncAttributeMaxDynamicSharedMemorySize, kSmem);
    cudaFuncSetAttribute(hmma_gemm<3>, cudaFuncAttributeMaxDynamicSharedMemorySize, kSmem);
    cudaFuncSetAttribute(hmma_gemm<4>, cudaFuncAttributeMaxDynamicSharedMemorySize, kSmem);

    const dim3 tb(32, 8);
    const dim3 gCC(kC / 32, kC / 32);
    wsplitT<<<gCC, tb>>>(Wk,  wkh, wkl, kC, kC);
    wsplitT<<<gCC, tb>>>(Wv,  wvh, wvl, kC, kC);
    wsplitT<<<gCC, tb>>>(Wr,  wrh, wrl, kC, kC);
    wsplitT<<<gCC, tb>>>(Wo,  woh, wol, kC, kC);
    wsplitT<<<dim3(kHID / 32, kC / 32), tb>>>(fWk, fkh, fkl, kC, kHID);   // [3072,768]
    wsplitT<<<dim3(kC / 32, kHID / 32), tb>>>(fWv, fvh, fvl, kHID, kC);   // [768,3072]
    wsplitT<<<gCC, tb>>>(fWr, frh, frl, kC, kC);

    const dim3 gC(kC / 128, kN / 128);     // (6, 196)
    const dim3 gH(kHID / 128, kN / 128);   // (24, 196)

    // --- attention branch ---
    ln0ln1_kernel<<<kN, 256>>>(x, ln0_g, ln0_b, ln1_g, ln1_b, px0, pxi);
    shiftmix_kernel<true><<<kNC / 256, 256>>>(pxi, amk, amv, amr, akh, akl, avh, avl, arh, arl);
    hmma_gemm<0><<<gC, 256, kSmem>>>(akh, akl, wkh, wkl, pk,  kC, kC, nullptr, nullptr);
    hmma_gemm<0><<<gC, 256, kSmem>>>(avh, avl, wvh, wvl, pv,  kC, kC, nullptr, nullptr);
    hmma_gemm<1><<<gC, 256, kSmem>>>(arh, arl, wrh, wrl, psr, kC, kC, nullptr, nullptr);
    wkv_kernel<<<kBC / 256, 256>>>(pk, pv, adecay, afirst, ptA, ptB, prw);
    // (sr * LN(rwkv)) -> planes (reuse av planes); sr multiplies BEFORE Wo
    ln_kernel<kC, true><<<kN, 256>>>(prw, akn_g, akn_b, psr, nullptr, avh, avl);
    hmma_gemm<4><<<gC, 256, kSmem>>>(avh, avl, woh, wol, px0, kC, kC, px0, nullptr);

    // --- FFN branch ---
    ln_kernel<kC, false><<<kN, 256>>>(px0, ln2_g, ln2_b, nullptr, pxi, nullptr, nullptr);
    shiftmix_kernel<false><<<kNC / 256, 256>>>(pxi, fmk, nullptr, fmr, akh, akl, nullptr, nullptr, arh, arl);
    hmma_gemm<2><<<gH, 256, kSmem>>>(akh, akl, fkh, fkl, phid, kC, kHID, nullptr, nullptr);  // relu^2
    ln_kernel<kHID, true><<<kN, 256>>>(phid, fkn_g, fkn_b, nullptr, nullptr, hh, hl);
    hmma_gemm<1><<<gC, 256, kSmem>>>(arh, arl, frh, frl, psr, kC, kC, nullptr, nullptr);     // sigmoid gate
    hmma_gemm<3><<<gC, 256, kSmem>>>(hh, hl, fvh, fvl, out, kHID, kC, px0, psr);             // out = x0 + gate*kv
}

// round 13
// speedup vs baseline: 1.3888x; 1.2919x over previous
#include <cuda_runtime.h>
#include <cuda_fp16.h>
#include <math.h>
#include <stdint.h>

// ---------------- constants ----------------
constexpr int kB   = 128;
constexpr int kT   = 196;
constexpr int kC   = 768;
constexpr int kHID = 3072;
constexpr int kH   = 14;
constexpr int kW   = 14;
constexpr int kN   = kB * kT;        // 25088 rows
constexpr int kNC  = kN * kC;
constexpr int kNH  = kN * kHID;
constexpr int kBC  = kB * kC;
constexpr float kEPS = 1e-5f;

// ---------------- scratch (device globals) ----------------
__device__ float g_x0[kNC];
__device__ float g_xi[kNC];
__device__ float g_k [kNC];
__device__ float g_v [kNC];
__device__ float g_sr[kNC];
__device__ float g_tA[kNC];
__device__ float g_tB[kNC];
__device__ float g_rw[kNC];
__device__ float g_hid[kNH];
// fp16 activation planes (hi/lo)
__device__ __half g_ak_h[kNC], g_ak_l[kNC];
__device__ __half g_av_h[kNC], g_av_l[kNC];
__device__ __half g_ar_h[kNC], g_ar_l[kNC];
__device__ __half g_hh [kNH],  g_hl [kNH];
// fp16 transposed weight planes [Mout, K] (hi only — Bl term dropped by design)
__device__ __half g_wk_h[kC*kC];
__device__ __half g_wv_h[kC*kC];
__device__ __half g_wr_h[kC*kC];
__device__ __half g_wo_h[kC*kC];
__device__ __half g_fk_h[kC*kHID];   // fWk^T [3072,768]
__device__ __half g_fv_h[kC*kHID];   // fWv^T [768,3072]
__device__ __half g_fr_h[kC*kC];

// ---------------- helpers ----------------
__device__ __forceinline__ uint32_t smem_u32(const void* p) {
    uint32_t a;
    asm("{ .reg .u64 t; cvta.to.shared.u64 t, %1; cvt.u32.u64 %0, t; }" : "=r"(a) : "l"(p));
    return a;
}
__device__ __forceinline__ uint32_t swz(uint32_t b) { return b ^ ((b >> 3) & 0x70); }

__device__ __forceinline__ void split2h(float x, __half& h, __half& l) {
    h = __float2half_rn(x);
    l = __float2half_rn(x - __half2float(h));
}

#define CP_ASYNC16(dst, src) \
    asm volatile("cp.async.cg.shared.global [%0], [%1], 16;" :: "r"(dst), "l"(src))
#define CP_COMMIT() asm volatile("cp.async.commit_group;" ::: "memory")
#define CP_WAIT0()  asm volatile("cp.async.wait_group 0;" ::: "memory")
#define CP_WAIT1()  asm volatile("cp.async.wait_group 1;" ::: "memory")

__device__ __forceinline__ void ldsm4(uint32_t& r0, uint32_t& r1, uint32_t& r2, uint32_t& r3, uint32_t addr) {
    asm volatile("ldmatrix.sync.aligned.m8n8.x4.shared.b16 {%0,%1,%2,%3}, [%4];"
                 : "=r"(r0), "=r"(r1), "=r"(r2), "=r"(r3) : "r"(addr));
}
__device__ __forceinline__ void mma16816(float* c, const uint32_t* a, const uint32_t* b) {
    asm volatile(
        "mma.sync.aligned.m16n8k16.row.col.f32.f16.f16.f32 "
        "{%0,%1,%2,%3}, {%4,%5,%6,%7}, {%8,%9}, {%0,%1,%2,%3};"
        : "+f"(c[0]), "+f"(c[1]), "+f"(c[2]), "+f"(c[3])
        : "r"(a[0]), "r"(a[1]), "r"(a[2]), "r"(a[3]), "r"(b[0]), "r"(b[1]));
}

// ---------------- HMMA GEMM, fp16 2-term split (Ah*Bh + Al*Bh), 128x128 tile ----------------
// C[N x M] = A[N x K] * W^T (W^T stored [M x K]); warp tile 64x32; 2-stage cp.async pipeline
// EPI: 0 none, 1 sigmoid, 2 relu^2, 3 res + s*acc, 4 res + acc
constexpr int kStageB = 48 * 1024;   // 3 planes x 16KB
template <int EPI>
__global__ void __launch_bounds__(256, 1)
hmma_gemm(const __half* __restrict__ Ah, const __half* __restrict__ Al,
          const __half* __restrict__ Bh,
          float* __restrict__ Cm, int K, int M,
          const float* __restrict__ res, const float* __restrict__ sg) {
    extern __shared__ char smem[];
    const uint32_t sb = smem_u32(smem);
    const int t = threadIdx.x, lane = t & 31, wid = t >> 5;
    const int rowBase = blockIdx.y * 128;
    const int colBase = blockIdx.x * 128;
    // warp tile: 64 rows x 32 cols
    const int mW = (wid & 1) * 64;
    const int nW = (wid >> 1) * 32;
    constexpr int SAH = 0, SAL = 16384, SBH = 32768;

    float acc[4][4][4];
    #pragma unroll
    for (int i = 0; i < 4; i++)
        #pragma unroll
        for (int j = 0; j < 4; j++)
            #pragma unroll
            for (int q = 0; q < 4; q++) acc[i][j][q] = 0.f;

    // global->smem: thread t loads half a 128B row (4x16B) of each plane
    const int lrow = t >> 1, lhalf = t & 1;
    const __half* gAh = Ah + (size_t)(rowBase + lrow) * K + lhalf * 32;
    const __half* gAl = Al + (size_t)(rowBase + lrow) * K + lhalf * 32;
    const __half* gBh = Bh + (size_t)(colBase + lrow) * K + lhalf * 32;
    uint32_t dst[4];
    #pragma unroll
    for (int i = 0; i < 4; i++) dst[i] = swz(lrow * 128 + lhalf * 64 + i * 16);

    const int nchunk = K >> 6;

    auto issue = [&](int kt, int stg) {
        const int ko = kt * 64;
        const uint32_t so = sb + stg * kStageB;
        #pragma unroll
        for (int i = 0; i < 4; i++) {
            CP_ASYNC16(so + SAH + dst[i], gAh + ko + i * 8);
            CP_ASYNC16(so + SAL + dst[i], gAl + ko + i * 8);
            CP_ASYNC16(so + SBH + dst[i], gBh + ko + i * 8);
        }
        CP_COMMIT();
    };

    // ldmatrix per-lane coords
    const int rA = lane & 15;
    const int kA = (lane >> 4) * 16;
    const int rB = (lane & 7) + ((lane >> 4) << 3);
    const int kB2 = ((lane >> 3) & 1) * 16;

    issue(0, 0);
    for (int kt = 0; kt < nchunk; ++kt) {
        const int cur = kt & 1;
        if (kt + 1 < nchunk) { issue(kt + 1, cur ^ 1); CP_WAIT1(); }
        else                 { CP_WAIT0(); }
        __syncthreads();
        const uint32_t so = sb + cur * kStageB;

        #pragma unroll
        for (int ks = 0; ks < 4; ++ks) {
            const int kbA = ks * 32 + kA;
            const int kbB = ks * 32 + kB2;
            uint32_t ah[4][4], al[4][4];
            #pragma unroll
            for (int mt = 0; mt < 4; mt++) {
                uint32_t off = swz((mW + mt * 16 + rA) * 128 + kbA);
                ldsm4(ah[mt][0], ah[mt][1], ah[mt][2], ah[mt][3], so + SAH + off);
                ldsm4(al[mt][0], al[mt][1], al[mt][2], al[mt][3], so + SAL + off);
            }
            uint32_t bh[4][2];
            #pragma unroll
            for (int p = 0; p < 2; p++) {
                uint32_t off = swz((nW + p * 16 + rB) * 128 + kbB);
                ldsm4(bh[2 * p][0], bh[2 * p][1], bh[2 * p + 1][0], bh[2 * p + 1][1], so + SBH + off);
            }
            #pragma unroll
            for (int mt = 0; mt < 4; mt++)
                #pragma unroll
                for (int nt = 0; nt < 4; nt++)
                    mma16816(acc[mt][nt], ah[mt], bh[nt]);
            #pragma unroll
            for (int mt = 0; mt < 4; mt++)
                #pragma unroll
                for (int nt = 0; nt < 4; nt++)
                    mma16816(acc[mt][nt], al[mt], bh[nt]);
        }
        __syncthreads();
    }

    // epilogue
    #pragma unroll
    for (int mt = 0; mt < 4; mt++) {
        const int r = rowBase + mW + mt * 16 + (lane >> 2);
        #pragma unroll
        for (int half = 0; half < 2; half++) {
            const int rr = r + half * 8;
            const size_t gb = (size_t)rr * M + colBase + nW + (lane & 3) * 2;
            #pragma unroll
            for (int nt = 0; nt < 4; nt++) {
                float2 v = make_float2(acc[mt][nt][half * 2], acc[mt][nt][half * 2 + 1]);
                const size_t o = gb + nt * 8;
                if (EPI == 1) {
                    v.x = 1.f / (1.f + expf(-v.x));
                    v.y = 1.f / (1.f + expf(-v.y));
                } else if (EPI == 2) {
                    v.x = fmaxf(v.x, 0.f); v.x *= v.x;
                    v.y = fmaxf(v.y, 0.f); v.y *= v.y;
                } else if (EPI == 3) {
                    float2 r2 = *(const float2*)&res[o];
                    float2 s2 = *(const float2*)&sg[o];
                    v.x = r2.x + s2.x * v.x;
                    v.y = r2.y + s2.y * v.y;
                } else if (EPI == 4) {
                    float2 r2 = *(const float2*)&res[o];
                    v.x += r2.x; v.y += r2.y;
                }
                *(float2*)&Cm[o] = v;
            }
        }
    }
}

// ---------------- weight transpose + fp16 hi plane ----------------
__global__ void wsplitT(const float* __restrict__ W, __half* __restrict__ hi, int K, int M) {
    __shared__ float tile[32][33];
    int m0 = blockIdx.x * 32, k0 = blockIdx.y * 32;
    int tx = threadIdx.x, ty = threadIdx.y;
    #pragma unroll
    for (int r = 0; r < 32; r += 8)
        tile[ty + r][tx] = W[(size_t)(k0 + ty + r) * M + m0 + tx];
    __syncthreads();
    #pragma unroll
    for (int r = 0; r < 32; r += 8) {
        float v = tile[tx][ty + r];
        hi[(size_t)(m0 + ty + r) * K + k0 + tx] = __float2half_rn(v);
    }
}

// ---------------- block-wide mean/rstd (blockDim.x == 256) ----------------
__device__ __forceinline__ void block_stats(float s, float s2, float& mean, float& rstd, float invL) {
    #pragma unroll
    for (int o = 16; o; o >>= 1) {
        s  += __shfl_xor_sync(0xffffffffu, s,  o);
        s2 += __shfl_xor_sync(0xffffffffu, s2, o);
    }
    __shared__ float sh[16];
    int lane = threadIdx.x & 31, w = threadIdx.x >> 5;
    if (lane == 0) { sh[w] = s; sh[8 + w] = s2; }
    __syncthreads();
    if (threadIdx.x == 0) {
        float ts = 0.f, ts2 = 0.f;
        #pragma unroll
        for (int i = 0; i < 8; i++) { ts += sh[i]; ts2 += sh[8 + i]; }
        float m = ts * invL;
        float var = ts2 * invL - m * m;
        sh[0] = m;
        sh[1] = rsqrtf(var + kEPS);
    }
    __syncthreads();
    mean = sh[0]; rstd = sh[1];
    __syncthreads();
}

// ---------------- ln0 -> x0, ln1(x0) -> xi ----------------
__global__ void ln0ln1_kernel(const float* __restrict__ x,
                              const float* __restrict__ g0, const float* __restrict__ b0,
                              const float* __restrict__ g1, const float* __restrict__ b1,
                              float* __restrict__ x0, float* __restrict__ xi) {
    int row = blockIdx.x, tid = threadIdx.x;
    const float* p = x + (size_t)row * kC;
    float v[3], s = 0.f, s2 = 0.f;
    #pragma unroll
    for (int i = 0; i < 3; i++) { v[i] = p[tid + i * 256]; s += v[i]; s2 += v[i] * v[i]; }
    float m, rs;
    block_stats(s, s2, m, rs, 1.f / kC);
    float y[3];
    s = 0.f; s2 = 0.f;
    #pragma unroll
    for (int i = 0; i < 3; i++) {
        int c = tid + i * 256;
        y[i] = (v[i] - m) * rs * g0[c] + b0[c];
        x0[(size_t)row * kC + c] = y[i];
        s += y[i]; s2 += y[i] * y[i];
    }
    block_stats(s, s2, m, rs, 1.f / kC);
    #pragma unroll
    for (int i = 0; i < 3; i++) {
        int c = tid + i * 256;
        xi[(size_t)row * kC + c] = (y[i] - m) * rs * g1[c] + b1[c];
    }
}

// ---------------- generic LN; OUTP=true -> fp16 hi/lo planes (optional *sMul) ----------------
template <int L, bool OUTP>
__global__ void ln_kernel(const float* __restrict__ in, const float* __restrict__ g,
                          const float* __restrict__ b, const float* __restrict__ sMul,
                          float* __restrict__ outF,
                          __half* __restrict__ outH, __half* __restrict__ outL) {
    constexpr int PT = L / 256;
    int row = blockIdx.x, tid = threadIdx.x;
    const float* p = in + (size_t)row * L;
    float v[PT], s = 0.f, s2 = 0.f;
    #pragma unroll
    for (int i = 0; i < PT; i++) { v[i] = p[tid + i * 256]; s += v[i]; s2 += v[i] * v[i]; }
    float m, rs;
    block_stats(s, s2, m, rs, 1.f / L);
    #pragma unroll
    for (int i = 0; i < PT; i++) {
        int c = tid + i * 256;
        size_t o = (size_t)row * L + c;
        float y = (v[i] - m) * rs * g[c] + b[c];
        if (sMul != nullptr) y *= sMul[o];
        if (OUTP) {
            __half h, l;
            split2h(y, h, l);
            outH[o] = h; outL[o] = l;
        } else {
            outF[o] = y;
        }
    }
}

// ---------------- q_shift + token mixes -> fp16 planes ----------------
template <bool HASV>
__global__ void shiftmix_kernel(const float* __restrict__ xi,
                                const float* __restrict__ mk, const float* __restrict__ mv,
                                const float* __restrict__ mr,
                                __half* __restrict__ kh, __half* __restrict__ kl,
                                __half* __restrict__ vh, __half* __restrict__ vl,
                                __half* __restrict__ rh, __half* __restrict__ rl) {
    int idx = blockIdx.x * 256 + threadIdx.x;
    if (idx >= kNC) return;
    int c = idx % kC;
    int n = idx / kC;
    int t = n % kT;
    int h = t / kW;
    int w = t % kW;
    int grp = c / (kC / 4);
    int hh = h, ww = w;
    bool ok;
    if (grp == 0)      { ww = w - 1; ok = (ww >= 0);  }
    else if (grp == 1) { ww = w + 1; ok = (ww < kW);  }
    else if (grp == 2) { hh = h - 1; ok = (hh >= 0);  }
    else               { hh = h + 1; ok = (hh < kH);  }
    float xx = 0.f;
    float xiv = xi[idx];
    if (ok) {
        int n2 = (n - t) + hh * kW + ww;
        xx = xi[(size_t)n2 * kC + c];
    }
    __half hB, lB;
    float a = mk[c];
    split2h(xiv * a + xx * (1.f - a), hB, lB); kh[idx] = hB; kl[idx] = lB;
    if (HASV) {
        a = mv[c];
        split2h(xiv * a + xx * (1.f - a), hB, lB); vh[idx] = hB; vl[idx] = lB;
    }
    a = mr[c];
    split2h(xiv * a + xx * (1.f - a), hB, lB); rh[idx] = hB; rl[idx] = lB;
}

// ---------------- bidirectional WKV ----------------
__global__ void wkv_kernel(const float* __restrict__ k, const float* __restrict__ v,
                           const float* __restrict__ decay, const float* __restrict__ first,
                           float* __restrict__ tA, float* __restrict__ tB,
                           float* __restrict__ out) {
    int idx = blockIdx.x * 256 + threadIdx.x;
    if (idx >= kBC) return;
    int b = idx / kC;
    int c = idx % kC;
    float wv = decay[c] * (1.f / kT);
    float u  = first[c] * (1.f / kT);
    float d  = expf(-wv);
    float ew = expf(wv);
    size_t base = (size_t)b * kT * kC + c;

    float kmax = -3.4e38f;
    for (int t = 0; t < kT; t++) kmax = fmaxf(kmax, k[base + (size_t)t * kC]);

    float a = 0.f, bb = 0.f;
    for (int t = kT - 1; t >= 0; --t) {
        size_t o = base + (size_t)t * kC;
        tA[o] = a; tB[o] = bb;
        float ek = expf(k[o] - kmax);
        a  = d * (a  + ek * v[o]);
        bb = d * (bb + ek);
    }
    a = 0.f; bb = 0.f;
    for (int t = 0; t < kT; t++) {
        size_t o = base + (size_t)t * kC;
        float kk = k[o];
        float vv = v[o];
        float ek = expf(kk - kmax);
        float eu = expf(u + kk - kmax);
        float num = ew * (a  + tA[o]) + eu * vv;
        float den = ew * (bb + tB[o]) + eu;
        out[o] = num / den;
        a  = d * (a  + ek * vv);
        bb = d * (bb + ek);
    }
}

// ---------------- launch ----------------
extern "C" void kernel_launch(void* const* d_in, const int* in_sizes, int n_in,
                              void* d_out, int out_size) {
    const float* x      = (const float*)d_in[0];
    const float* ln0_g  = (const float*)d_in[1];
    const float* ln0_b  = (const float*)d_in[2];
    const float* ln1_g  = (const float*)d_in[3];
    const float* ln1_b  = (const float*)d_in[4];
    const float* ln2_g  = (const float*)d_in[5];
    const float* ln2_b  = (const float*)d_in[6];
    const float* amk    = (const float*)d_in[7];
    const float* amv    = (const float*)d_in[8];
    const float* amr    = (const float*)d_in[9];
    const float* adecay = (const float*)d_in[10];
    const float* afirst = (const float*)d_in[11];
    const float* Wk     = (const float*)d_in[12];
    const float* Wv     = (const float*)d_in[13];
    const float* Wr     = (const float*)d_in[14];
    const float* Wo     = (const float*)d_in[15];
    const float* akn_g  = (const float*)d_in[16];
    const float* akn_b  = (const float*)d_in[17];
    const float* fmk    = (const float*)d_in[18];
    const float* fmr    = (const float*)d_in[19];
    const float* fWk    = (const float*)d_in[20];
    const float* fWv    = (const float*)d_in[21];
    const float* fWr    = (const float*)d_in[22];
    const float* fkn_g  = (const float*)d_in[23];
    const float* fkn_b  = (const float*)d_in[24];
    float* out = (float*)d_out;

    float *px0, *pxi, *pk, *pv, *psr, *ptA, *ptB, *prw, *phid;
    cudaGetSymbolAddress((void**)&px0,  g_x0);
    cudaGetSymbolAddress((void**)&pxi,  g_xi);
    cudaGetSymbolAddress((void**)&pk,   g_k);
    cudaGetSymbolAddress((void**)&pv,   g_v);
    cudaGetSymbolAddress((void**)&psr,  g_sr);
    cudaGetSymbolAddress((void**)&ptA,  g_tA);
    cudaGetSymbolAddress((void**)&ptB,  g_tB);
    cudaGetSymbolAddress((void**)&prw,  g_rw);
    cudaGetSymbolAddress((void**)&phid, g_hid);

    __half *akh, *akl, *avh, *avl, *arh, *arl, *hh, *hl;
    cudaGetSymbolAddress((void**)&akh, g_ak_h); cudaGetSymbolAddress((void**)&akl, g_ak_l);
    cudaGetSymbolAddress((void**)&avh, g_av_h); cudaGetSymbolAddress((void**)&avl, g_av_l);
    cudaGetSymbolAddress((void**)&arh, g_ar_h); cudaGetSymbolAddress((void**)&arl, g_ar_l);
    cudaGetSymbolAddress((void**)&hh,  g_hh);   cudaGetSymbolAddress((void**)&hl,  g_hl);

    __half *wkh, *wvh, *wrh, *woh, *fkh, *fvh, *frh;
    cudaGetSymbolAddress((void**)&wkh, g_wk_h);
    cudaGetSymbolAddress((void**)&wvh, g_wv_h);
    cudaGetSymbolAddress((void**)&wrh, g_wr_h);
    cudaGetSymbolAddress((void**)&woh, g_wo_h);
    cudaGetSymbolAddress((void**)&fkh, g_fk_h);
    cudaGetSymbolAddress((void**)&fvh, g_fv_h);
    cudaGetSymbolAddress((void**)&frh, g_fr_h);

    constexpr int kSmem = 2 * kStageB;   // 96 KB
    cudaFuncSetAttribute(hmma_gemm<0>, cudaFuncAttributeMaxDynamicSharedMemorySize, kSmem);
    cudaFuncSetAttribute(hmma_gemm<1>, cudaFuncAttributeMaxDynamicSharedMemorySize, kSmem);
    cudaFuncSetAttribute(hmma_gemm<2>, cudaFuncAttributeMaxDynamicSharedMemorySize, kSmem);
    cudaFuncSetAttribute(hmma_gemm<3>, cudaFuncAttributeMaxDynamicSharedMemorySize, kSmem);
    cudaFuncSetAttribute(hmma_gemm<4>, cudaFuncAttributeMaxDynamicSharedMemorySize, kSmem);

    const dim3 tb(32, 8);
    const dim3 gCC(kC / 32, kC / 32);
    wsplitT<<<gCC, tb>>>(Wk,  wkh, kC, kC);
    wsplitT<<<gCC, tb>>>(Wv,  wvh, kC, kC);
    wsplitT<<<gCC, tb>>>(Wr,  wrh, kC, kC);
    wsplitT<<<gCC, tb>>>(Wo,  woh, kC, kC);
    wsplitT<<<dim3(kHID / 32, kC / 32), tb>>>(fWk, fkh, kC, kHID);   // [3072,768]
    wsplitT<<<dim3(kC / 32, kHID / 32), tb>>>(fWv, fvh, kHID, kC);   // [768,3072]
    wsplitT<<<gCC, tb>>>(fWr, frh, kC, kC);

    const dim3 gC(kC / 128, kN / 128);     // (6, 196)
    const dim3 gH(kHID / 128, kN / 128);   // (24, 196)

    // --- attention branch ---
    ln0ln1_kernel<<<kN, 256>>>(x, ln0_g, ln0_b, ln1_g, ln1_b, px0, pxi);
    shiftmix_kernel<true><<<kNC / 256, 256>>>(pxi, amk, amv, amr, akh, akl, avh, avl, arh, arl);
    hmma_gemm<0><<<gC, 256, kSmem>>>(akh, akl, wkh, pk,  kC, kC, nullptr, nullptr);
    hmma_gemm<0><<<gC, 256, kSmem>>>(avh, avl, wvh, pv,  kC, kC, nullptr, nullptr);
    hmma_gemm<1><<<gC, 256, kSmem>>>(arh, arl, wrh, psr, kC, kC, nullptr, nullptr);
    wkv_kernel<<<kBC / 256, 256>>>(pk, pv, adecay, afirst, ptA, ptB, prw);
    // (sr * LN(rwkv)) -> planes (reuse av planes); sr multiplies BEFORE Wo
    ln_kernel<kC, true><<<kN, 256>>>(prw, akn_g, akn_b, psr, nullptr, avh, avl);
    hmma_gemm<4><<<gC, 256, kSmem>>>(avh, avl, woh, px0, kC, kC, px0, nullptr);

    // --- FFN branch ---
    ln_kernel<kC, false><<<kN, 256>>>(px0, ln2_g, ln2_b, nullptr, pxi, nullptr, nullptr);
    shiftmix_kernel<false><<<kNC / 256, 256>>>(pxi, fmk, nullptr, fmr, akh, akl, nullptr, nullptr, arh, arl);
    hmma_gemm<2><<<gH, 256, kSmem>>>(akh, akl, fkh, phid, kC, kHID, nullptr, nullptr);  // relu^2
    ln_kernel<kHID, true><<<kN, 256>>>(phid, fkn_g, fkn_b, nullptr, nullptr, hh, hl);
    hmma_gemm<1><<<gC, 256, kSmem>>>(arh, arl, frh, psr, kC, kC, nullptr, nullptr);     // sigmoid gate
    hmma_gemm<3><<<gC, 256, kSmem>>>(hh, hl, fvh, out, kHID, kC, px0, psr);             // out = x0 + gate*kv
}

// round 14
// speedup vs baseline: 1.4933x; 1.0752x over previous
#include <cuda_runtime.h>
#include <cuda_fp16.h>
#include <math.h>
#include <stdint.h>

// ---------------- constants ----------------
constexpr int kB   = 128;
constexpr int kT   = 196;
constexpr int kC   = 768;
constexpr int kHID = 3072;
constexpr int kH   = 14;
constexpr int kW   = 14;
constexpr int kN   = kB * kT;        // 25088 rows
constexpr int kNC  = kN * kC;
constexpr int kNH  = kN * kHID;
constexpr int kBC  = kB * kC;
constexpr float kEPS = 1e-5f;

// ---------------- scratch (device globals) ----------------
__device__ float g_x0[kNC];
__device__ float g_xi[kNC];
__device__ float g_k [kNC];
__device__ float g_v [kNC];
__device__ float g_sr[kNC];
__device__ float g_tA[kNC];
__device__ float g_tB[kNC];
__device__ float g_rw[kNC];
__device__ float g_hid[kNH];
// fp16 activation planes (hi/lo)
__device__ __half g_ak_h[kNC], g_ak_l[kNC];
__device__ __half g_av_h[kNC], g_av_l[kNC];
__device__ __half g_ar_h[kNC], g_ar_l[kNC];
__device__ __half g_hh [kNH],  g_hl [kNH];
// fp16 transposed weight planes [Mout, K] (hi only — Bl term dropped by design)
__device__ __half g_wk_h[kC*kC];
__device__ __half g_wv_h[kC*kC];
__device__ __half g_wr_h[kC*kC];
__device__ __half g_wo_h[kC*kC];
__device__ __half g_fk_h[kC*kHID];   // fWk^T [3072,768]
__device__ __half g_fv_h[kC*kHID];   // fWv^T [768,3072]
__device__ __half g_fr_h[kC*kC];

// ---------------- helpers ----------------
__device__ __forceinline__ uint32_t smem_u32(const void* p) {
    uint32_t a;
    asm("{ .reg .u64 t; cvta.to.shared.u64 t, %1; cvt.u32.u64 %0, t; }" : "=r"(a) : "l"(p));
    return a;
}
__device__ __forceinline__ uint32_t swz(uint32_t b) { return b ^ ((b >> 3) & 0x70); }

__device__ __forceinline__ void split2h(float x, __half& h, __half& l) {
    h = __float2half_rn(x);
    l = __float2half_rn(x - __half2float(h));
}

#define CP_ASYNC16(dst, src) \
    asm volatile("cp.async.cg.shared.global [%0], [%1], 16;" :: "r"(dst), "l"(src))
#define CP_COMMIT() asm volatile("cp.async.commit_group;" ::: "memory")
#define CP_WAIT0()  asm volatile("cp.async.wait_group 0;" ::: "memory")
#define CP_WAIT1()  asm volatile("cp.async.wait_group 1;" ::: "memory")

__device__ __forceinline__ void ldsm4(uint32_t& r0, uint32_t& r1, uint32_t& r2, uint32_t& r3, uint32_t addr) {
    asm volatile("ldmatrix.sync.aligned.m8n8.x4.shared.b16 {%0,%1,%2,%3}, [%4];"
                 : "=r"(r0), "=r"(r1), "=r"(r2), "=r"(r3) : "r"(addr));
}
__device__ __forceinline__ void mma16816(float* c, const uint32_t* a, const uint32_t* b) {
    asm volatile(
        "mma.sync.aligned.m16n8k16.row.col.f32.f16.f16.f32 "
        "{%0,%1,%2,%3}, {%4,%5,%6,%7}, {%8,%9}, {%0,%1,%2,%3};"
        : "+f"(c[0]), "+f"(c[1]), "+f"(c[2]), "+f"(c[3])
        : "r"(a[0]), "r"(a[1]), "r"(a[2]), "r"(a[3]), "r"(b[0]), "r"(b[1]));
}

// ---------------- HMMA GEMM, fp16 2-term split (Ah*Bh + Al*Bh), 128x128 tile ----------------
// C[N x M] = A[N x K] * W^T (W^T stored [M x K]); warp tile 64x32; 2-stage pipeline; occ=2
// EPI: 0 none, 1 sigmoid, 2 relu^2, 3 res + s*acc, 4 res + acc
constexpr int kStageB = 48 * 1024;   // 3 planes x 16KB
template <int EPI>
__global__ void __launch_bounds__(256, 2)
hmma_gemm(const __half* __restrict__ Ah, const __half* __restrict__ Al,
          const __half* __restrict__ Bh,
          float* __restrict__ Cm, int K, int M,
          const float* __restrict__ res, const float* __restrict__ sg) {
    extern __shared__ char smem[];
    const uint32_t sb = smem_u32(smem);
    const int t = threadIdx.x, lane = t & 31, wid = t >> 5;
    const int rowBase = blockIdx.y * 128;
    const int colBase = blockIdx.x * 128;
    // warp tile: 64 rows x 32 cols
    const int mW = (wid & 1) * 64;
    const int nW = (wid >> 1) * 32;
    constexpr int SAH = 0, SAL = 16384, SBH = 32768;

    float acc[4][4][4];
    #pragma unroll
    for (int i = 0; i < 4; i++)
        #pragma unroll
        for (int j = 0; j < 4; j++)
            #pragma unroll
            for (int q = 0; q < 4; q++) acc[i][j][q] = 0.f;

    // global->smem: thread t loads half a 128B row (4x16B) of each plane
    const int lrow = t >> 1, lhalf = t & 1;
    const __half* gAh = Ah + (size_t)(rowBase + lrow) * K + lhalf * 32;
    const __half* gAl = Al + (size_t)(rowBase + lrow) * K + lhalf * 32;
    const __half* gBh = Bh + (size_t)(colBase + lrow) * K + lhalf * 32;
    uint32_t dst[4];
    #pragma unroll
    for (int i = 0; i < 4; i++) dst[i] = swz(lrow * 128 + lhalf * 64 + i * 16);

    const int nchunk = K >> 6;

    auto issue = [&](int kt, int stg) {
        const int ko = kt * 64;
        const uint32_t so = sb + stg * kStageB;
        #pragma unroll
        for (int i = 0; i < 4; i++) {
            CP_ASYNC16(so + SAH + dst[i], gAh + ko + i * 8);
            CP_ASYNC16(so + SAL + dst[i], gAl + ko + i * 8);
            CP_ASYNC16(so + SBH + dst[i], gBh + ko + i * 8);
        }
        CP_COMMIT();
    };

    // ldmatrix per-lane coords
    const int rA = lane & 15;
    const int kA = (lane >> 4) * 16;
    const int rB = (lane & 7) + ((lane >> 4) << 3);
    const int kB2 = ((lane >> 3) & 1) * 16;

    issue(0, 0);
    for (int kt = 0; kt < nchunk; ++kt) {
        const int cur = kt & 1;
        if (kt + 1 < nchunk) { issue(kt + 1, cur ^ 1); CP_WAIT1(); }
        else                 { CP_WAIT0(); }
        __syncthreads();
        const uint32_t so = sb + cur * kStageB;

        #pragma unroll
        for (int ks = 0; ks < 4; ++ks) {
            const int kbA = ks * 32 + kA;
            const int kbB = ks * 32 + kB2;
            uint32_t ah[4][4], al[4][4];
            #pragma unroll
            for (int mt = 0; mt < 4; mt++) {
                uint32_t off = swz((mW + mt * 16 + rA) * 128 + kbA);
                ldsm4(ah[mt][0], ah[mt][1], ah[mt][2], ah[mt][3], so + SAH + off);
                ldsm4(al[mt][0], al[mt][1], al[mt][2], al[mt][3], so + SAL + off);
            }
            uint32_t bh[4][2];
            #pragma unroll
            for (int p = 0; p < 2; p++) {
                uint32_t off = swz((nW + p * 16 + rB) * 128 + kbB);
                ldsm4(bh[2 * p][0], bh[2 * p][1], bh[2 * p + 1][0], bh[2 * p + 1][1], so + SBH + off);
            }
            #pragma unroll
            for (int mt = 0; mt < 4; mt++)
                #pragma unroll
                for (int nt = 0; nt < 4; nt++)
                    mma16816(acc[mt][nt], ah[mt], bh[nt]);
            #pragma unroll
            for (int mt = 0; mt < 4; mt++)
                #pragma unroll
                for (int nt = 0; nt < 4; nt++)
                    mma16816(acc[mt][nt], al[mt], bh[nt]);
        }
        __syncthreads();
    }

    // epilogue
    #pragma unroll
    for (int mt = 0; mt < 4; mt++) {
        const int r = rowBase + mW + mt * 16 + (lane >> 2);
        #pragma unroll
        for (int half = 0; half < 2; half++) {
            const int rr = r + half * 8;
            const size_t gb = (size_t)rr * M + colBase + nW + (lane & 3) * 2;
            #pragma unroll
            for (int nt = 0; nt < 4; nt++) {
                float2 v = make_float2(acc[mt][nt][half * 2], acc[mt][nt][half * 2 + 1]);
                const size_t o = gb + nt * 8;
                if (EPI == 1) {
                    v.x = 1.f / (1.f + expf(-v.x));
                    v.y = 1.f / (1.f + expf(-v.y));
                } else if (EPI == 2) {
                    v.x = fmaxf(v.x, 0.f); v.x *= v.x;
                    v.y = fmaxf(v.y, 0.f); v.y *= v.y;
                } else if (EPI == 3) {
                    float2 r2 = *(const float2*)&res[o];
                    float2 s2 = *(const float2*)&sg[o];
                    v.x = r2.x + s2.x * v.x;
                    v.y = r2.y + s2.y * v.y;
                } else if (EPI == 4) {
                    float2 r2 = *(const float2*)&res[o];
                    v.x += r2.x; v.y += r2.y;
                }
                *(float2*)&Cm[o] = v;
            }
        }
    }
}

// ---------------- weight transpose + fp16 hi plane ----------------
__global__ void wsplitT(const float* __restrict__ W, __half* __restrict__ hi, int K, int M) {
    __shared__ float tile[32][33];
    int m0 = blockIdx.x * 32, k0 = blockIdx.y * 32;
    int tx = threadIdx.x, ty = threadIdx.y;
    #pragma unroll
    for (int r = 0; r < 32; r += 8)
        tile[ty + r][tx] = W[(size_t)(k0 + ty + r) * M + m0 + tx];
    __syncthreads();
    #pragma unroll
    for (int r = 0; r < 32; r += 8) {
        float v = tile[tx][ty + r];
        hi[(size_t)(m0 + ty + r) * K + k0 + tx] = __float2half_rn(v);
    }
}

// ---------------- block-wide mean/rstd (blockDim.x == 256) ----------------
__device__ __forceinline__ void block_stats(float s, float s2, float& mean, float& rstd, float invL) {
    #pragma unroll
    for (int o = 16; o; o >>= 1) {
        s  += __shfl_xor_sync(0xffffffffu, s,  o);
        s2 += __shfl_xor_sync(0xffffffffu, s2, o);
    }
    __shared__ float sh[16];
    int lane = threadIdx.x & 31, w = threadIdx.x >> 5;
    if (lane == 0) { sh[w] = s; sh[8 + w] = s2; }
    __syncthreads();
    if (threadIdx.x == 0) {
        float ts = 0.f, ts2 = 0.f;
        #pragma unroll
        for (int i = 0; i < 8; i++) { ts += sh[i]; ts2 += sh[8 + i]; }
        float m = ts * invL;
        float var = ts2 * invL - m * m;
        sh[0] = m;
        sh[1] = rsqrtf(var + kEPS);
    }
    __syncthreads();
    mean = sh[0]; rstd = sh[1];
    __syncthreads();
}

// ---------------- ln0 -> x0, ln1(x0) -> xi ----------------
__global__ void ln0ln1_kernel(const float* __restrict__ x,
                              const float* __restrict__ g0, const float* __restrict__ b0,
                              const float* __restrict__ g1, const float* __restrict__ b1,
                              float* __restrict__ x0, float* __restrict__ xi) {
    int row = blockIdx.x, tid = threadIdx.x;
    const float* p = x + (size_t)row * kC;
    float v[3], s = 0.f, s2 = 0.f;
    #pragma unroll
    for (int i = 0; i < 3; i++) { v[i] = p[tid + i * 256]; s += v[i]; s2 += v[i] * v[i]; }
    float m, rs;
    block_stats(s, s2, m, rs, 1.f / kC);
    float y[3];
    s = 0.f; s2 = 0.f;
    #pragma unroll
    for (int i = 0; i < 3; i++) {
        int c = tid + i * 256;
        y[i] = (v[i] - m) * rs * g0[c] + b0[c];
        x0[(size_t)row * kC + c] = y[i];
        s += y[i]; s2 += y[i] * y[i];
    }
    block_stats(s, s2, m, rs, 1.f / kC);
    #pragma unroll
    for (int i = 0; i < 3; i++) {
        int c = tid + i * 256;
        xi[(size_t)row * kC + c] = (y[i] - m) * rs * g1[c] + b1[c];
    }
}

// ---------------- generic LN; OUTP=true -> fp16 hi/lo planes (optional *sMul) ----------------
template <int L, bool OUTP>
__global__ void ln_kernel(const float* __restrict__ in, const float* __restrict__ g,
                          const float* __restrict__ b, const float* __restrict__ sMul,
                          float* __restrict__ outF,
                          __half* __restrict__ outH, __half* __restrict__ outL) {
    constexpr int PT = L / 256;
    int row = blockIdx.x, tid = threadIdx.x;
    const float* p = in + (size_t)row * L;
    float v[PT], s = 0.f, s2 = 0.f;
    #pragma unroll
    for (int i = 0; i < PT; i++) { v[i] = p[tid + i * 256]; s += v[i]; s2 += v[i] * v[i]; }
    float m, rs;
    block_stats(s, s2, m, rs, 1.f / L);
    #pragma unroll
    for (int i = 0; i < PT; i++) {
        int c = tid + i * 256;
        size_t o = (size_t)row * L + c;
        float y = (v[i] - m) * rs * g[c] + b[c];
        if (sMul != nullptr) y *= sMul[o];
        if (OUTP) {
            __half h, l;
            split2h(y, h, l);
            outH[o] = h; outL[o] = l;
        } else {
            outF[o] = y;
        }
    }
}

// ---------------- q_shift + token mixes -> fp16 planes ----------------
template <bool HASV>
__global__ void shiftmix_kernel(const float* __restrict__ xi,
                                const float* __restrict__ mk, const float* __restrict__ mv,
                                const float* __restrict__ mr,
                                __half* __restrict__ kh, __half* __restrict__ kl,
                                __half* __restrict__ vh, __half* __restrict__ vl,
                                __half* __restrict__ rh, __half* __restrict__ rl) {
    int idx = blockIdx.x * 256 + threadIdx.x;
    if (idx >= kNC) return;
    int c = idx % kC;
    int n = idx / kC;
    int t = n % kT;
    int h = t / kW;
    int w = t % kW;
    int grp = c / (kC / 4);
    int hh = h, ww = w;
    bool ok;
    if (grp == 0)      { ww = w - 1; ok = (ww >= 0);  }
    else if (grp == 1) { ww = w + 1; ok = (ww < kW);  }
    else if (grp == 2) { hh = h - 1; ok = (hh >= 0);  }
    else               { hh = h + 1; ok = (hh < kH);  }
    float xx = 0.f;
    float xiv = xi[idx];
    if (ok) {
        int n2 = (n - t) + hh * kW + ww;
        xx = xi[(size_t)n2 * kC + c];
    }
    __half hB, lB;
    float a = mk[c];
    split2h(xiv * a + xx * (1.f - a), hB, lB); kh[idx] = hB; kl[idx] = lB;
    if (HASV) {
        a = mv[c];
        split2h(xiv * a + xx * (1.f - a), hB, lB); vh[idx] = hB; vl[idx] = lB;
    }
    a = mr[c];
    split2h(xiv * a + xx * (1.f - a), hB, lB); rh[idx] = hB; rl[idx] = lB;
}

// ---------------- bidirectional WKV ----------------
__global__ void wkv_kernel(const float* __restrict__ k, const float* __restrict__ v,
                           const float* __restrict__ decay, const float* __restrict__ first,
                           float* __restrict__ tA, float* __restrict__ tB,
                           float* __restrict__ out) {
    int idx = blockIdx.x * 256 + threadIdx.x;
    if (idx >= kBC) return;
    int b = idx / kC;
    int c = idx % kC;
    float wv = decay[c] * (1.f / kT);
    float u  = first[c] * (1.f / kT);
    float d  = expf(-wv);
    float ew = expf(wv);
    size_t base = (size_t)b * kT * kC + c;

    float kmax = -3.4e38f;
    for (int t = 0; t < kT; t++) kmax = fmaxf(kmax, k[base + (size_t)t * kC]);

    float a = 0.f, bb = 0.f;
    for (int t = kT - 1; t >= 0; --t) {
        size_t o = base + (size_t)t * kC;
        tA[o] = a; tB[o] = bb;
        float ek = expf(k[o] - kmax);
        a  = d * (a  + ek * v[o]);
        bb = d * (bb + ek);
    }
    a = 0.f; bb = 0.f;
    for (int t = 0; t < kT; t++) {
        size_t o = base + (size_t)t * kC;
        float kk = k[o];
        float vv = v[o];
        float ek = expf(kk - kmax);
        float eu = expf(u + kk - kmax);
        float num = ew * (a  + tA[o]) + eu * vv;
        float den = ew * (bb + tB[o]) + eu;
        out[o] = num / den;
        a  = d * (a  + ek * vv);
        bb = d * (bb + ek);
    }
}

// ---------------- launch ----------------
extern "C" void kernel_launch(void* const* d_in, const int* in_sizes, int n_in,
                              void* d_out, int out_size) {
    const float* x      = (const float*)d_in[0];
    const float* ln0_g  = (const float*)d_in[1];
    const float* ln0_b  = (const float*)d_in[2];
    const float* ln1_g  = (const float*)d_in[3];
    const float* ln1_b  = (const float*)d_in[4];
    const float* ln2_g  = (const float*)d_in[5];
    const float* ln2_b  = (const float*)d_in[6];
    const float* amk    = (const float*)d_in[7];
    const float* amv    = (const float*)d_in[8];
    const float* amr    = (const float*)d_in[9];
    const float* adecay = (const float*)d_in[10];
    const float* afirst = (const float*)d_in[11];
    const float* Wk     = (const float*)d_in[12];
    const float* Wv     = (const float*)d_in[13];
    const float* Wr     = (const float*)d_in[14];
    const float* Wo     = (const float*)d_in[15];
    const float* akn_g  = (const float*)d_in[16];
    const float* akn_b  = (const float*)d_in[17];
    const float* fmk    = (const float*)d_in[18];
    const float* fmr    = (const float*)d_in[19];
    const float* fWk    = (const float*)d_in[20];
    const float* fWv    = (const float*)d_in[21];
    const float* fWr    = (const float*)d_in[22];
    const float* fkn_g  = (const float*)d_in[23];
    const float* fkn_b  = (const float*)d_in[24];
    float* out = (float*)d_out;

    float *px0, *pxi, *pk, *pv, *psr, *ptA, *ptB, *prw, *phid;
    cudaGetSymbolAddress((void**)&px0,  g_x0);
    cudaGetSymbolAddress((void**)&pxi,  g_xi);
    cudaGetSymbolAddress((void**)&pk,   g_k);
    cudaGetSymbolAddress((void**)&pv,   g_v);
    cudaGetSymbolAddress((void**)&psr,  g_sr);
    cudaGetSymbolAddress((void**)&ptA,  g_tA);
    cudaGetSymbolAddress((void**)&ptB,  g_tB);
    cudaGetSymbolAddress((void**)&prw,  g_rw);
    cudaGetSymbolAddress((void**)&phid, g_hid);

    __half *akh, *akl, *avh, *avl, *arh, *arl, *hh, *hl;
    cudaGetSymbolAddress((void**)&akh, g_ak_h); cudaGetSymbolAddress((void**)&akl, g_ak_l);
    cudaGetSymbolAddress((void**)&avh, g_av_h); cudaGetSymbolAddress((void**)&avl, g_av_l);
    cudaGetSymbolAddress((void**)&arh, g_ar_h); cudaGetSymbolAddress((void**)&arl, g_ar_l);
    cudaGetSymbolAddress((void**)&hh,  g_hh);   cudaGetSymbolAddress((void**)&hl,  g_hl);

    __half *wkh, *wvh, *wrh, *woh, *fkh, *fvh, *frh;
    cudaGetSymbolAddress((void**)&wkh, g_wk_h);
    cudaGetSymbolAddress((void**)&wvh, g_wv_h);
    cudaGetSymbolAddress((void**)&wrh, g_wr_h);
    cudaGetSymbolAddress((void**)&woh, g_wo_h);
    cudaGetSymbolAddress((void**)&fkh, g_fk_h);
    cudaGetSymbolAddress((void**)&fvh, g_fv_h);
    cudaGetSymbolAddress((void**)&frh, g_fr_h);

    constexpr int kSmem = 2 * kStageB;   // 96 KB per CTA -> 2 CTAs/SM
    cudaFuncSetAttribute(hmma_gemm<0>, cudaFuncAttributeMaxDynamicSharedMemorySize, kSmem);
    cudaFuncSetAttribute(hmma_gemm<1>, cudaFuncAttributeMaxDynamicSharedMemorySize, kSmem);
    cudaFuncSetAttribute(hmma_gemm<2>, cudaFuncAttributeMaxDynamicSharedMemorySize, kSmem);
    cudaFuncSetAttribute(hmma_gemm<3>, cudaFuncAttributeMaxDynamicSharedMemorySize, kSmem);
    cudaFuncSetAttribute(hmma_gemm<4>, cudaFuncAttributeMaxDynamicSharedMemorySize, kSmem);

    const dim3 tb(32, 8);
    const dim3 gCC(kC / 32, kC / 32);
    wsplitT<<<gCC, tb>>>(Wk,  wkh, kC, kC);
    wsplitT<<<gCC, tb>>>(Wv,  wvh, kC, kC);
    wsplitT<<<gCC, tb>>>(Wr,  wrh, kC, kC);
    wsplitT<<<gCC, tb>>>(Wo,  woh, kC, kC);
    wsplitT<<<dim3(kHID / 32, kC / 32), tb>>>(fWk, fkh, kC, kHID);   // [3072,768]
    wsplitT<<<dim3(kC / 32, kHID / 32), tb>>>(fWv, fvh, kHID, kC);   // [768,3072]
    wsplitT<<<gCC, tb>>>(fWr, frh, kC, kC);

    const dim3 gC(kC / 128, kN / 128);     // (6, 196)
    const dim3 gH(kHID / 128, kN / 128);   // (24, 196)

    // --- attention branch ---
    ln0ln1_kernel<<<kN, 256>>>(x, ln0_g, ln0_b, ln1_g, ln1_b, px0, pxi);
    shiftmix_kernel<true><<<kNC / 256, 256>>>(pxi, amk, amv, amr, akh, akl, avh, avl, arh, arl);
    hmma_gemm<0><<<gC, 256, kSmem>>>(akh, akl, wkh, pk,  kC, kC, nullptr, nullptr);
    hmma_gemm<0><<<gC, 256, kSmem>>>(avh, avl, wvh, pv,  kC, kC, nullptr, nullptr);
    hmma_gemm<1><<<gC, 256, kSmem>>>(arh, arl, wrh, psr, kC, kC, nullptr, nullptr);
    wkv_kernel<<<kBC / 256, 256>>>(pk, pv, adecay, afirst, ptA, ptB, prw);
    // (sr * LN(rwkv)) -> planes (reuse av planes); sr multiplies BEFORE Wo
    ln_kernel<kC, true><<<kN, 256>>>(prw, akn_g, akn_b, psr, nullptr, avh, avl);
    hmma_gemm<4><<<gC, 256, kSmem>>>(avh, avl, woh, px0, kC, kC, px0, nullptr);

    // --- FFN branch ---
    ln_kernel<kC, false><<<kN, 256>>>(px0, ln2_g, ln2_b, nullptr, pxi, nullptr, nullptr);
    shiftmix_kernel<false><<<kNC / 256, 256>>>(pxi, fmk, nullptr, fmr, akh, akl, nullptr, nullptr, arh, arl);
    hmma_gemm<2><<<gH, 256, kSmem>>>(akh, akl, fkh, phid, kC, kHID, nullptr, nullptr);  // relu^2
    ln_kernel<kHID, true><<<kN, 256>>>(phid, fkn_g, fkn_b, nullptr, nullptr, hh, hl);
    hmma_gemm<1><<<gC, 256, kSmem>>>(arh, arl, frh, psr, kC, kC, nullptr, nullptr);     // sigmoid gate
    hmma_gemm<3><<<gC, 256, kSmem>>>(hh, hl, fvh, out, kHID, kC, px0, psr);             // out = x0 + gate*kv
}

// round 17
// speedup vs baseline: 1.5816x; 1.0591x over previous
#include <cuda_runtime.h>
#include <cuda_fp16.h>
#include <math.h>
#include <stdint.h>

// ---------------- constants ----------------
constexpr int kB   = 128;
constexpr int kT   = 196;
constexpr int kC   = 768;
constexpr int kHID = 3072;
constexpr int kH   = 14;
constexpr int kW   = 14;
constexpr int kN   = kB * kT;        // 25088 rows
constexpr int kNC  = kN * kC;
constexpr int kNH  = kN * kHID;
constexpr int kBC  = kB * kC;
constexpr float kEPS = 1e-5f;

// ---------------- scratch (device globals) ----------------
__device__ float g_x0[kNC];
__device__ float g_xi[kNC];
__device__ float g_k [kNC];
__device__ float g_v [kNC];
__device__ float g_sr[kNC];
__device__ float g_tA[kNC];
__device__ float g_tB[kNC];
__device__ float g_rw[kNC];
__device__ float g_hid[kNH];
// fp16 activation planes (hi/lo)
__device__ __half g_ak_h[kNC], g_ak_l[kNC];
__device__ __half g_av_h[kNC], g_av_l[kNC];
__device__ __half g_ar_h[kNC];               // gate path: hi only
__device__ __half g_hh [kNH],  g_hl [kNH];
// fp16 transposed weight planes [Mout, K] (hi only — Bl term dropped by design)
__device__ __half g_wk_h[kC*kC];
__device__ __half g_wv_h[kC*kC];
__device__ __half g_wr_h[kC*kC];
__device__ __half g_wo_h[kC*kC];
__device__ __half g_fk_h[kC*kHID];   // fWk^T [3072,768]
__device__ __half g_fv_h[kC*kHID];   // fWv^T [768,3072]
__device__ __half g_fr_h[kC*kC];

// ---------------- helpers ----------------
__device__ __forceinline__ uint32_t smem_u32(const void* p) {
    uint32_t a;
    asm("{ .reg .u64 t; cvta.to.shared.u64 t, %1; cvt.u32.u64 %0, t; }" : "=r"(a) : "l"(p));
    return a;
}
__device__ __forceinline__ uint32_t swz(uint32_t b) { return b ^ ((b >> 3) & 0x70); }

__device__ __forceinline__ void split2h(float x, __half& h, __half& l) {
    h = __float2half_rn(x);
    l = __float2half_rn(x - __half2float(h));
}

#define CP_ASYNC16(dst, src) \
    asm volatile("cp.async.cg.shared.global [%0], [%1], 16;" :: "r"(dst), "l"(src))
#define CP_COMMIT() asm volatile("cp.async.commit_group;" ::: "memory")
#define CP_WAIT0()  asm volatile("cp.async.wait_group 0;" ::: "memory")
#define CP_WAIT1()  asm volatile("cp.async.wait_group 1;" ::: "memory")

__device__ __forceinline__ void ldsm4(uint32_t& r0, uint32_t& r1, uint32_t& r2, uint32_t& r3, uint32_t addr) {
    asm volatile("ldmatrix.sync.aligned.m8n8.x4.shared.b16 {%0,%1,%2,%3}, [%4];"
                 : "=r"(r0), "=r"(r1), "=r"(r2), "=r"(r3) : "r"(addr));
}
__device__ __forceinline__ void mma16816(float* c, const uint32_t* a, const uint32_t* b) {
    asm volatile(
        "mma.sync.aligned.m16n8k16.row.col.f32.f16.f16.f32 "
        "{%0,%1,%2,%3}, {%4,%5,%6,%7}, {%8,%9}, {%0,%1,%2,%3};"
        : "+f"(c[0]), "+f"(c[1]), "+f"(c[2]), "+f"(c[3])
        : "r"(a[0]), "r"(a[1]), "r"(a[2]), "r"(a[3]), "r"(b[0]), "r"(b[1]));
}

// ---------------- HMMA GEMM, fp16 split, 128x128 tile, 2-stage pipeline, occ=2 ----------------
// C[N x M] = A[N x K] * W^T (W^T stored [M x K]); warp tile 64x32
// EPI: 0 none, 1 sigmoid, 2 relu^2, 3 res + s*acc, 4 res + acc
// NT : number of A split terms (2 = Ah*Bh + Al*Bh; 1 = Ah*Bh only)
constexpr int kStageB = 48 * 1024;   // up to 3 planes x 16KB
template <int EPI, int NT>
__global__ void __launch_bounds__(256, 2)
hmma_gemm(const __half* __restrict__ Ah, const __half* __restrict__ Al,
          const __half* __restrict__ Bh,
          float* __restrict__ Cm, int K, int M,
          const float* __restrict__ res, const float* __restrict__ sg) {
    extern __shared__ char smem[];
    const uint32_t sb = smem_u32(smem);
    const int t = threadIdx.x, lane = t & 31, wid = t >> 5;
    const int rowBase = blockIdx.y * 128;
    const int colBase = blockIdx.x * 128;
    // warp tile: 64 rows x 32 cols
    const int mW = (wid & 1) * 64;
    const int nW = (wid >> 1) * 32;
    constexpr int SAH = 0, SAL = 16384, SBH = 32768;

    float acc[4][4][4];
    #pragma unroll
    for (int i = 0; i < 4; i++)
        #pragma unroll
        for (int j = 0; j < 4; j++)
            #pragma unroll
            for (int q = 0; q < 4; q++) acc[i][j][q] = 0.f;

    // global->smem: thread t loads half a 128B row (4x16B) of each plane
    const int lrow = t >> 1, lhalf = t & 1;
    const __half* gAh = Ah + (size_t)(rowBase + lrow) * K + lhalf * 32;
    const __half* gAl = (NT == 2) ? Al + (size_t)(rowBase + lrow) * K + lhalf * 32 : nullptr;
    const __half* gBh = Bh + (size_t)(colBase + lrow) * K + lhalf * 32;
    uint32_t dst[4];
    #pragma unroll
    for (int i = 0; i < 4; i++) dst[i] = swz(lrow * 128 + lhalf * 64 + i * 16);

    const int nchunk = K >> 6;

    auto issue = [&](int kt, int stg) {
        const int ko = kt * 64;
        const uint32_t so = sb + stg * kStageB;
        #pragma unroll
        for (int i = 0; i < 4; i++) {
            CP_ASYNC16(so + SAH + dst[i], gAh + ko + i * 8);
            if (NT == 2) CP_ASYNC16(so + SAL + dst[i], gAl + ko + i * 8);
            CP_ASYNC16(so + SBH + dst[i], gBh + ko + i * 8);
        }
        CP_COMMIT();
    };

    // ldmatrix per-lane coords
    const int rA = lane & 15;
    const int kA = (lane >> 4) * 16;
    const int rB = (lane & 7) + ((lane >> 4) << 3);
    const int kB2 = ((lane >> 3) & 1) * 16;

    issue(0, 0);
    for (int kt = 0; kt < nchunk; ++kt) {
        const int cur = kt & 1;
        if (kt + 1 < nchunk) { issue(kt + 1, cur ^ 1); CP_WAIT1(); }
        else                 { CP_WAIT0(); }
        __syncthreads();
        const uint32_t so = sb + cur * kStageB;

        #pragma unroll
        for (int ks = 0; ks < 4; ++ks) {
            const int kbA = ks * 32 + kA;
            const int kbB = ks * 32 + kB2;
            uint32_t ah[4][4], al[4][4];
            #pragma unroll
            for (int mt = 0; mt < 4; mt++) {
                uint32_t off = swz((mW + mt * 16 + rA) * 128 + kbA);
                ldsm4(ah[mt][0], ah[mt][1], ah[mt][2], ah[mt][3], so + SAH + off);
                if (NT == 2)
                    ldsm4(al[mt][0], al[mt][1], al[mt][2], al[mt][3], so + SAL + off);
            }
            uint32_t bh[4][2];
            #pragma unroll
            for (int p = 0; p < 2; p++) {
                uint32_t off = swz((nW + p * 16 + rB) * 128 + kbB);
                ldsm4(bh[2 * p][0], bh[2 * p][1], bh[2 * p + 1][0], bh[2 * p + 1][1], so + SBH + off);
            }
            #pragma unroll
            for (int mt = 0; mt < 4; mt++)
                #pragma unroll
                for (int nt = 0; nt < 4; nt++)
                    mma16816(acc[mt][nt], ah[mt], bh[nt]);
            if (NT == 2) {
                #pragma unroll
                for (int mt = 0; mt < 4; mt++)
                    #pragma unroll
                    for (int nt = 0; nt < 4; nt++)
                        mma16816(acc[mt][nt], al[mt], bh[nt]);
            }
        }
        __syncthreads();
    }

    // epilogue
    #pragma unroll
    for (int mt = 0; mt < 4; mt++) {
        const int r = rowBase + mW + mt * 16 + (lane >> 2);
        #pragma unroll
        for (int half = 0; half < 2; half++) {
            const int rr = r + half * 8;
            const size_t gb = (size_t)rr * M + colBase + nW + (lane & 3) * 2;
            #pragma unroll
            for (int nt = 0; nt < 4; nt++) {
                float2 v = make_float2(acc[mt][nt][half * 2], acc[mt][nt][half * 2 + 1]);
                const size_t o = gb + nt * 8;
                if (EPI == 1) {
                    v.x = 1.f / (1.f + expf(-v.x));
                    v.y = 1.f / (1.f + expf(-v.y));
                } else if (EPI == 2) {
                    v.x = fmaxf(v.x, 0.f); v.x *= v.x;
                    v.y = fmaxf(v.y, 0.f); v.y *= v.y;
                } else if (EPI == 3) {
                    float2 r2 = *(const float2*)&res[o];
                    float2 s2 = *(const float2*)&sg[o];
                    v.x = r2.x + s2.x * v.x;
                    v.y = r2.y + s2.y * v.y;
                } else if (EPI == 4) {
                    float2 r2 = *(const float2*)&res[o];
                    v.x += r2.x; v.y += r2.y;
                }
                *(float2*)&Cm[o] = v;
            }
        }
    }
}

// ---------------- weight transpose + fp16 hi plane ----------------
__global__ void wsplitT(const float* __restrict__ W, __half* __restrict__ hi, int K, int M) {
    __shared__ float tile[32][33];
    int m0 = blockIdx.x * 32, k0 = blockIdx.y * 32;
    int tx = threadIdx.x, ty = threadIdx.y;
    #pragma unroll
    for (int r = 0; r < 32; r += 8)
        tile[ty + r][tx] = W[(size_t)(k0 + ty + r) * M + m0 + tx];
    __syncthreads();
    #pragma unroll
    for (int r = 0; r < 32; r += 8) {
        float v = tile[tx][ty + r];
        hi[(size_t)(m0 + ty + r) * K + k0 + tx] = __float2half_rn(v);
    }
}

// ---------------- block-wide mean/rstd (blockDim.x == 256) ----------------
__device__ __forceinline__ void block_stats(float s, float s2, float& mean, float& rstd, float invL) {
    #pragma unroll
    for (int o = 16; o; o >>= 1) {
        s  += __shfl_xor_sync(0xffffffffu, s,  o);
        s2 += __shfl_xor_sync(0xffffffffu, s2, o);
    }
    __shared__ float sh[16];
    int lane = threadIdx.x & 31, w = threadIdx.x >> 5;
    if (lane == 0) { sh[w] = s; sh[8 + w] = s2; }
    __syncthreads();
    if (threadIdx.x == 0) {
        float ts = 0.f, ts2 = 0.f;
        #pragma unroll
        for (int i = 0; i < 8; i++) { ts += sh[i]; ts2 += sh[8 + i]; }
        float m = ts * invL;
        float var = ts2 * invL - m * m;
        sh[0] = m;
        sh[1] = rsqrtf(var + kEPS);
    }
    __syncthreads();
    mean = sh[0]; rstd = sh[1];
    __syncthreads();
}

// ---------------- ln0 -> x0, ln1(x0) -> xi ----------------
__global__ void ln0ln1_kernel(const float* __restrict__ x,
                              const float* __restrict__ g0, const float* __restrict__ b0,
                              const float* __restrict__ g1, const float* __restrict__ b1,
                              float* __restrict__ x0, float* __restrict__ xi) {
    int row = blockIdx.x, tid = threadIdx.x;
    const float* p = x + (size_t)row * kC;
    float v[3], s = 0.f, s2 = 0.f;
    #pragma unroll
    for (int i = 0; i < 3; i++) { v[i] = p[tid + i * 256]; s += v[i]; s2 += v[i] * v[i]; }
    float m, rs;
    block_stats(s, s2, m, rs, 1.f / kC);
    float y[3];
    s = 0.f; s2 = 0.f;
    #pragma unroll
    for (int i = 0; i < 3; i++) {
        int c = tid + i * 256;
        y[i] = (v[i] - m) * rs * g0[c] + b0[c];
        x0[(size_t)row * kC + c] = y[i];
        s += y[i]; s2 += y[i] * y[i];
    }
    block_stats(s, s2, m, rs, 1.f / kC);
    #pragma unroll
    for (int i = 0; i < 3; i++) {
        int c = tid + i * 256;
        xi[(size_t)row * kC + c] = (y[i] - m) * rs * g1[c] + b1[c];
    }
}

// ---------------- generic LN; OUTP=true -> fp16 hi/lo planes (optional *sMul) ----------------
template <int L, bool OUTP>
__global__ void ln_kernel(const float* __restrict__ in, const float* __restrict__ g,
                          const float* __restrict__ b, const float* __restrict__ sMul,
                          float* __restrict__ outF,
                          __half* __restrict__ outH, __half* __restrict__ outL) {
    constexpr int PT = L / 256;
    int row = blockIdx.x, tid = threadIdx.x;
    const float* p = in + (size_t)row * L;
    float v[PT], s = 0.f, s2 = 0.f;
    #pragma unroll
    for (int i = 0; i < PT; i++) { v[i] = p[tid + i * 256]; s += v[i]; s2 += v[i] * v[i]; }
    float m, rs;
    block_stats(s, s2, m, rs, 1.f / L);
    #pragma unroll
    for (int i = 0; i < PT; i++) {
        int c = tid + i * 256;
        size_t o = (size_t)row * L + c;
        float y = (v[i] - m) * rs * g[c] + b[c];
        if (sMul != nullptr) y *= sMul[o];
        if (OUTP) {
            __half h, l;
            split2h(y, h, l);
            outH[o] = h; outL[o] = l;
        } else {
            outF[o] = y;
        }
    }
}

// ---------------- q_shift + token mixes -> fp16 planes (lo planes optional) ----------------
template <bool HASV>
__global__ void shiftmix_kernel(const float* __restrict__ xi,
                                const float* __restrict__ mk, const float* __restrict__ mv,
                                const float* __restrict__ mr,
                                __half* __restrict__ kh, __half* __restrict__ kl,
                                __half* __restrict__ vh, __half* __restrict__ vl,
                                __half* __restrict__ rh, __half* __restrict__ rl) {
    int idx = blockIdx.x * 256 + threadIdx.x;
    if (idx >= kNC) return;
    int c = idx % kC;
    int n = idx / kC;
    int t = n % kT;
    int h = t / kW;
    int w = t % kW;
    int grp = c / (kC / 4);
    int hh = h, ww = w;
    bool ok;
    if (grp == 0)      { ww = w - 1; ok = (ww >= 0);  }
    else if (grp == 1) { ww = w + 1; ok = (ww < kW);  }
    else if (grp == 2) { hh = h - 1; ok = (hh >= 0);  }
    else               { hh = h + 1; ok = (hh < kH);  }
    float xx = 0.f;
    float xiv = xi[idx];
    if (ok) {
        int n2 = (n - t) + hh * kW + ww;
        xx = xi[(size_t)n2 * kC + c];
    }
    __half hB, lB;
    float a = mk[c];
    split2h(xiv * a + xx * (1.f - a), hB, lB);
    kh[idx] = hB;
    if (kl != nullptr) kl[idx] = lB;
    if (HASV) {
        a = mv[c];
        split2h(xiv * a + xx * (1.f - a), hB, lB);
        vh[idx] = hB;
        if (vl != nullptr) vl[idx] = lB;
    }
    a = mr[c];
    split2h(xiv * a + xx * (1.f - a), hB, lB);
    rh[idx] = hB;
    if (rl != nullptr) rl[idx] = lB;
}

// ---------------- bidirectional WKV ----------------
__global__ void wkv_kernel(const float* __restrict__ k, const float* __restrict__ v,
                           const float* __restrict__ decay, const float* __restrict__ first,
                           float* __restrict__ tA, float* __restrict__ tB,
                           float* __restrict__ out) {
    int idx = blockIdx.x * 256 + threadIdx.x;
    if (idx >= kBC) return;
    int b = idx / kC;
    int c = idx % kC;
    float wv = decay[c] * (1.f / kT);
    float u  = first[c] * (1.f / kT);
    float d  = expf(-wv);
    float ew = expf(wv);
    size_t base = (size_t)b * kT * kC + c;

    float kmax = -3.4e38f;
    for (int t = 0; t < kT; t++) kmax = fmaxf(kmax, k[base + (size_t)t * kC]);

    float a = 0.f, bb = 0.f;
    for (int t = kT - 1; t >= 0; --t) {
        size_t o = base + (size_t)t * kC;
        tA[o] = a; tB[o] = bb;
        float ek = expf(k[o] - kmax);
        a  = d * (a  + ek * v[o]);
        bb = d * (bb + ek);
    }
    a = 0.f; bb = 0.f;
    for (int t = 0; t < kT; t++) {
        size_t o = base + (size_t)t * kC;
        float kk = k[o];
        float vv = v[o];
        float ek = expf(kk - kmax);
        float eu = expf(u + kk - kmax);
        float num = ew * (a  + tA[o]) + eu * vv;
        float den = ew * (bb + tB[o]) + eu;
        out[o] = num / den;
        a  = d * (a  + ek * vv);
        bb = d * (bb + ek);
    }
}

// ---------------- launch ----------------
extern "C" void kernel_launch(void* const* d_in, const int* in_sizes, int n_in,
                              void* d_out, int out_size) {
    const float* x      = (const float*)d_in[0];
    const float* ln0_g  = (const float*)d_in[1];
    const float* ln0_b  = (const float*)d_in[2];
    const float* ln1_g  = (const float*)d_in[3];
    const float* ln1_b  = (const float*)d_in[4];
    const float* ln2_g  = (const float*)d_in[5];
    const float* ln2_b  = (const float*)d_in[6];
    const float* amk    = (const float*)d_in[7];
    const float* amv    = (const float*)d_in[8];
    const float* amr    = (const float*)d_in[9];
    const float* adecay = (const float*)d_in[10];
    const float* afirst = (const float*)d_in[11];
    const float* Wk     = (const float*)d_in[12];
    const float* Wv     = (const float*)d_in[13];
    const float* Wr     = (const float*)d_in[14];
    const float* Wo     = (const float*)d_in[15];
    const float* akn_g  = (const float*)d_in[16];
    const float* akn_b  = (const float*)d_in[17];
    const float* fmk    = (const float*)d_in[18];
    const float* fmr    = (const float*)d_in[19];
    const float* fWk    = (const float*)d_in[20];
    const float* fWv    = (const float*)d_in[21];
    const float* fWr    = (const float*)d_in[22];
    const float* fkn_g  = (const float*)d_in[23];
    const float* fkn_b  = (const float*)d_in[24];
    float* out = (float*)d_out;

    float *px0, *pxi, *pk, *pv, *psr, *ptA, *ptB, *prw, *phid;
    cudaGetSymbolAddress((void**)&px0,  g_x0);
    cudaGetSymbolAddress((void**)&pxi,  g_xi);
    cudaGetSymbolAddress((void**)&pk,   g_k);
    cudaGetSymbolAddress((void**)&pv,   g_v);
    cudaGetSymbolAddress((void**)&psr,  g_sr);
    cudaGetSymbolAddress((void**)&ptA,  g_tA);
    cudaGetSymbolAddress((void**)&ptB,  g_tB);
    cudaGetSymbolAddress((void**)&prw,  g_rw);
    cudaGetSymbolAddress((void**)&phid, g_hid);

    __half *akh, *akl, *avh, *avl, *arh, *hh, *hl;
    cudaGetSymbolAddress((void**)&akh, g_ak_h); cudaGetSymbolAddress((void**)&akl, g_ak_l);
    cudaGetSymbolAddress((void**)&avh, g_av_h); cudaGetSymbolAddress((void**)&avl, g_av_l);
    cudaGetSymbolAddress((void**)&arh, g_ar_h);
    cudaGetSymbolAddress((void**)&hh,  g_hh);   cudaGetSymbolAddress((void**)&hl,  g_hl);

    __half *wkh, *wvh, *wrh, *woh, *fkh, *fvh, *frh;
    cudaGetSymbolAddress((void**)&wkh, g_wk_h);
    cudaGetSymbolAddress((void**)&wvh, g_wv_h);
    cudaGetSymbolAddress((void**)&wrh, g_wr_h);
    cudaGetSymbolAddress((void**)&woh, g_wo_h);
    cudaGetSymbolAddress((void**)&fkh, g_fk_h);
    cudaGetSymbolAddress((void**)&fvh, g_fv_h);
    cudaGetSymbolAddress((void**)&frh, g_fr_h);

    constexpr int kSmem = 2 * kStageB;   // 96 KB per CTA -> 2 CTAs/SM
    cudaFuncSetAttribute(hmma_gemm<0,2>, cudaFuncAttributeMaxDynamicSharedMemorySize, kSmem);
    cudaFuncSetAttribute(hmma_gemm<1,1>, cudaFuncAttributeMaxDynamicSharedMemorySize, kSmem);
    cudaFuncSetAttribute(hmma_gemm<2,2>, cudaFuncAttributeMaxDynamicSharedMemorySize, kSmem);
    cudaFuncSetAttribute(hmma_gemm<3,2>, cudaFuncAttributeMaxDynamicSharedMemorySize, kSmem);
    cudaFuncSetAttribute(hmma_gemm<4,2>, cudaFuncAttributeMaxDynamicSharedMemorySize, kSmem);

    const dim3 tb(32, 8);
    const dim3 gCC(kC / 32, kC / 32);
    wsplitT<<<gCC, tb>>>(Wk,  wkh, kC, kC);
    wsplitT<<<gCC, tb>>>(Wv,  wvh, kC, kC);
    wsplitT<<<gCC, tb>>>(Wr,  wrh, kC, kC);
    wsplitT<<<gCC, tb>>>(Wo,  woh, kC, kC);
    wsplitT<<<dim3(kHID / 32, kC / 32), tb>>>(fWk, fkh, kC, kHID);   // [3072,768]
    wsplitT<<<dim3(kC / 32, kHID / 32), tb>>>(fWv, fvh, kHID, kC);   // [768,3072]
    wsplitT<<<gCC, tb>>>(fWr, frh, kC, kC);

    const dim3 gC(kC / 128, kN / 128);     // (6, 196)
    const dim3 gH(kHID / 128, kN / 128);   // (24, 196)

    // --- attention branch ---
    ln0ln1_kernel<<<kN, 256>>>(x, ln0_g, ln0_b, ln1_g, ln1_b, px0, pxi);
    shiftmix_kernel<true><<<kNC / 256, 256>>>(pxi, amk, amv, amr, akh, akl, avh, avl, arh, nullptr);
    hmma_gemm<0,2><<<gC, 256, kSmem>>>(akh, akl, wkh, pk,  kC, kC, nullptr, nullptr);
    hmma_gemm<0,2><<<gC, 256, kSmem>>>(avh, avl, wvh, pv,  kC, kC, nullptr, nullptr);
    hmma_gemm<1,1><<<gC, 256, kSmem>>>(arh, nullptr, wrh, psr, kC, kC, nullptr, nullptr);   // sigmoid gate
    wkv_kernel<<<kBC / 256, 256>>>(pk, pv, adecay, afirst, ptA, ptB, prw);
    // (sr * LN(rwkv)) -> planes (reuse av planes); sr multiplies BEFORE Wo
    ln_kernel<kC, true><<<kN, 256>>>(prw, akn_g, akn_b, psr, nullptr, avh, avl);
    hmma_gemm<4,2><<<gC, 256, kSmem>>>(avh, avl, woh, px0, kC, kC, px0, nullptr);

    // --- FFN branch ---
    ln_kernel<kC, false><<<kN, 256>>>(px0, ln2_g, ln2_b, nullptr, pxi, nullptr, nullptr);
    shiftmix_kernel<false><<<kNC / 256, 256>>>(pxi, fmk, nullptr, fmr, akh, akl, nullptr, nullptr, arh, nullptr);
    hmma_gemm<2,2><<<gH, 256, kSmem>>>(akh, akl, fkh, phid, kC, kHID, nullptr, nullptr);  // relu^2
    ln_kernel<kHID, true><<<kN, 256>>>(phid, fkn_g, fkn_b, nullptr, nullptr, hh, hl);
    hmma_gemm<1,1><<<gC, 256, kSmem>>>(arh, nullptr, frh, psr, kC, kC, nullptr, nullptr);  // sigmoid gate
    hmma_gemm<3,2><<<gC, 256, kSmem>>>(hh, hl, fvh, out, kHID, kC, px0, psr);              // out = x0 + gate*kv
}